// round 2
// baseline (speedup 1.0000x reference)
#include <cuda_runtime.h>
#include <math.h>

// ---------------- problem constants ----------------
#define B_    4
#define H_    8
#define LQ_   2048
#define LK_   2048
#define DH_   64
#define D_    512
#define KTOP  205

// ---------------- device scratch (no allocations allowed) ----------------
__device__ float g_qn[(size_t)B_ * H_ * LQ_ * DH_];   // 16 MB
__device__ float g_kn[(size_t)B_ * H_ * LK_ * DH_];   // 16 MB
__device__ float g_vv[(size_t)B_ * H_ * LK_ * DH_];   // 16 MB
__device__ float g_sc[(size_t)B_ * H_ * LQ_ * LK_];   // 512 MB
__device__ float g_ctx[(size_t)B_ * LQ_ * D_];        // 16 MB

// ---------------- accurate expf, fast-math-proof (~1 ulp) ----------------
__device__ __forceinline__ float exp_rn(float x) {
    if (x < -87.0f) return 0.0f;
    float n = rintf(__fmul_rn(x, 1.4426950408889634f));
    float f = __fmaf_rn(-n, 0.6931471824645996f, x);
    f = __fmaf_rn(-n, -1.9046543e-09f, f);
    float p = 1.9841269841e-04f;               // 1/5040
    p = __fmaf_rn(p, f, 1.3888888889e-03f);    // 1/720
    p = __fmaf_rn(p, f, 8.3333333333e-03f);    // 1/120
    p = __fmaf_rn(p, f, 4.1666666667e-02f);    // 1/24
    p = __fmaf_rn(p, f, 1.6666666667e-01f);    // 1/6
    p = __fmaf_rn(p, f, 0.5f);
    p = __fmaf_rn(p, f, 1.0f);
    p = __fmaf_rn(p, f, 1.0f);
    return ldexpf(p, (int)n);
}

// =====================================================================
// GEMM: C = A(MxK) * Bt(NxK)^T, 128x128 tile, K-chunk 8, 8x8 microtile.
// EPI 0: projection epilogue -> g layout [b,h,l,e], +bias, optional tanh
// EPI 1: scores epilogue     -> C[m*N+n] = acc * scale   (batched via z)
// EPI 2: out-proj epilogue   -> C[m*N+n] = acc + bias[n]
// =====================================================================
template<int EPI>
__global__ __launch_bounds__(256, 2)
void gemm_bt_kernel(const float* __restrict__ A, const float* __restrict__ Bt,
                    const float* __restrict__ bias, float* __restrict__ C,
                    int M, int N, int K, int lda, int ldb,
                    size_t strideA, size_t strideB, size_t strideC,
                    int do_tanh, float scale)
{
    __shared__ float As[2][8][128];
    __shared__ float Bs[2][8][128];
    const int z = blockIdx.z;
    A  += strideA * (size_t)z;
    Bt += strideB * (size_t)z;
    C  += strideC * (size_t)z;

    const int m0 = blockIdx.y * 128;
    const int n0 = blockIdx.x * 128;
    const int t  = threadIdx.x;

    const int lrow = t >> 1;            // 0..127
    const int lcol = (t & 1) << 2;      // 0 or 4
    const float* Ald = A  + (size_t)(m0 + lrow) * lda + lcol;
    const float* Bld = Bt + (size_t)(n0 + lrow) * ldb + lcol;

    const int mi = (t >> 4) << 3;
    const int ni = (t & 15) << 3;

    float acc[8][8];
#pragma unroll
    for (int i = 0; i < 8; i++)
#pragma unroll
        for (int j = 0; j < 8; j++) acc[i][j] = 0.0f;

    float4 av = *(const float4*)Ald;
    float4 bv = *(const float4*)Bld;
    As[0][lcol+0][lrow]=av.x; As[0][lcol+1][lrow]=av.y; As[0][lcol+2][lrow]=av.z; As[0][lcol+3][lrow]=av.w;
    Bs[0][lcol+0][lrow]=bv.x; Bs[0][lcol+1][lrow]=bv.y; Bs[0][lcol+2][lrow]=bv.z; Bs[0][lcol+3][lrow]=bv.w;
    __syncthreads();

    const int nc = K >> 3;
    for (int c = 0; c < nc; ++c) {
        const int cur = c & 1;
        if (c + 1 < nc) {
            av = *(const float4*)(Ald + (c + 1) * 8);
            bv = *(const float4*)(Bld + (c + 1) * 8);
        }
#pragma unroll
        for (int kc = 0; kc < 8; ++kc) {
            float a[8], b[8];
            *(float4*)(a)     = *(const float4*)&As[cur][kc][mi];
            *(float4*)(a + 4) = *(const float4*)&As[cur][kc][mi + 4];
            *(float4*)(b)     = *(const float4*)&Bs[cur][kc][ni];
            *(float4*)(b + 4) = *(const float4*)&Bs[cur][kc][ni + 4];
#pragma unroll
            for (int i = 0; i < 8; i++)
#pragma unroll
                for (int j = 0; j < 8; j++)
                    acc[i][j] = fmaf(a[i], b[j], acc[i][j]);
        }
        if (c + 1 < nc) {
            const int nxt = cur ^ 1;
            As[nxt][lcol+0][lrow]=av.x; As[nxt][lcol+1][lrow]=av.y; As[nxt][lcol+2][lrow]=av.z; As[nxt][lcol+3][lrow]=av.w;
            Bs[nxt][lcol+0][lrow]=bv.x; Bs[nxt][lcol+1][lrow]=bv.y; Bs[nxt][lcol+2][lrow]=bv.z; Bs[nxt][lcol+3][lrow]=bv.w;
            __syncthreads();
        }
    }

    if (EPI == 0) {
#pragma unroll
        for (int i = 0; i < 8; i++) {
            const int m  = m0 + mi + i;
            const int bb = m >> 11;          // / LQ_
            const int l  = m & (LQ_ - 1);
#pragma unroll
            for (int jj = 0; jj < 8; jj += 4) {
                const int n = n0 + ni + jj;
                const int h = n >> 6, e = n & 63;
                float4 o;
                o.x = acc[i][jj+0] + bias[n+0];
                o.y = acc[i][jj+1] + bias[n+1];
                o.z = acc[i][jj+2] + bias[n+2];
                o.w = acc[i][jj+3] + bias[n+3];
                if (do_tanh) { o.x = tanhf(o.x); o.y = tanhf(o.y); o.z = tanhf(o.z); o.w = tanhf(o.w); }
                const size_t off = (((size_t)(bb * H_ + h)) * LQ_ + l) * DH_ + e;
                *(float4*)(C + off) = o;
            }
        }
    } else if (EPI == 1) {
#pragma unroll
        for (int i = 0; i < 8; i++) {
            const size_t rb = (size_t)(m0 + mi + i) * N + n0 + ni;
#pragma unroll
            for (int jj = 0; jj < 8; jj += 4) {
                float4 o;
                o.x = acc[i][jj+0] * scale;
                o.y = acc[i][jj+1] * scale;
                o.z = acc[i][jj+2] * scale;
                o.w = acc[i][jj+3] * scale;
                *(float4*)(C + rb + jj) = o;
            }
        }
    } else {
#pragma unroll
        for (int i = 0; i < 8; i++) {
            const size_t rb = (size_t)(m0 + mi + i) * N + n0 + ni;
#pragma unroll
            for (int jj = 0; jj < 8; jj += 4) {
                const int n = n0 + ni + jj;
                float4 o;
                o.x = acc[i][jj+0] + bias[n+0];
                o.y = acc[i][jj+1] + bias[n+1];
                o.z = acc[i][jj+2] + bias[n+2];
                o.w = acc[i][jj+3] + bias[n+3];
                *(float4*)(C + rb + jj) = o;
            }
        }
    }
}

// ---------------- L2 normalize rows of 64 (warp per row) ----------------
__global__ __launch_bounds__(256)
void l2norm_kernel(float* __restrict__ X, int nrows)
{
    const int gw   = (blockIdx.x * blockDim.x + threadIdx.x) >> 5;
    const int lane = threadIdx.x & 31;
    if (gw >= nrows) return;
    float* r = X + (size_t)gw * DH_;
    float a = r[lane], b = r[lane + 32];
    float s = __fmaf_rn(a, a, __fmul_rn(b, b));
#pragma unroll
    for (int o = 16; o; o >>= 1) s += __shfl_xor_sync(0xffffffffu, s, o);
    float n = fmaxf(__fsqrt_rn(s), 1e-12f);
    r[lane]      = __fdiv_rn(a, n);
    r[lane + 32] = __fdiv_rn(b, n);
}

// =====================================================================
// Per-row: softmax -> smoothing -> gate -> exact top-205 mask (in place).
// One block (256 thr) per row; thread t owns elements [t*8, t*8+8).
// Exact k-th largest via binary search on uint bit patterns (all vals>=0),
// ties kept lowest-index-first (matches jax.lax.top_k / torch.topk).
// =====================================================================
__global__ __launch_bounds__(256)
void softmax_topk_kernel(float* __restrict__ S)
{
    __shared__ float shf[8];
    __shared__ int   shi[8];
    __shared__ float bcf;
    __shared__ int   bci;

    const int t    = threadIdx.x;
    const int lane = t & 31;
    const int w    = t >> 5;
    float* row = S + (size_t)blockIdx.x * LK_;

    float x[8];
    *(float4*)(x)     = *(const float4*)(row + t * 8);
    *(float4*)(x + 4) = *(const float4*)(row + t * 8 + 4);

    // ---- row max ----
    float m = x[0];
#pragma unroll
    for (int j = 1; j < 8; j++) m = fmaxf(m, x[j]);
#pragma unroll
    for (int o = 16; o; o >>= 1) m = fmaxf(m, __shfl_xor_sync(0xffffffffu, m, o));
    if (lane == 0) shf[w] = m;
    __syncthreads();
    if (t == 0) { float mm = shf[0];
#pragma unroll
        for (int i = 1; i < 8; i++) mm = fmaxf(mm, shf[i]);
        bcf = mm; }
    __syncthreads();
    m = bcf;

    // ---- exp + sum ----
    float e[8]; float s = 0.0f;
#pragma unroll
    for (int j = 0; j < 8; j++) { e[j] = exp_rn(__fadd_rn(x[j], -m)); s = __fadd_rn(s, e[j]); }
#pragma unroll
    for (int o = 16; o; o >>= 1) s += __shfl_xor_sync(0xffffffffu, s, o);
    if (lane == 0) shf[w] = s;
    __syncthreads();
    if (t == 0) { float ss = 0.0f;
#pragma unroll
        for (int i = 0; i < 8; i++) ss = __fadd_rn(ss, shf[i]);
        bcf = ss; }
    __syncthreads();
    s = bcf;

    // ---- smoothing + gate (exact single-rounding ops, matching ref order) ----
    const float SMC = (float)(0.01 / 2048.0);
    float a[8];
#pragma unroll
    for (int j = 0; j < 8; j++) {
        float p = __fdiv_rn(e[j], s);
        float q = __fadd_rn(__fmul_rn(0.99f, p), SMC);
        a[j] = (q >= 1e-4f) ? q : 0.0f;
    }

    // ---- exact k-th largest via bit-pattern binary search ----
    unsigned lo = 0u, hi = 0x7f7fffffu;
    while (lo < hi) {
        unsigned mid = lo + ((hi - lo + 1) >> 1);
        int c = 0;
#pragma unroll
        for (int j = 0; j < 8; j++) c += (__float_as_uint(a[j]) >= mid);
#pragma unroll
        for (int o = 16; o; o >>= 1) c += __shfl_xor_sync(0xffffffffu, c, o);
        if (lane == 0) shi[w] = c;
        __syncthreads();
        if (t == 0) { int tt = 0;
#pragma unroll
            for (int i = 0; i < 8; i++) tt += shi[i];
            bci = tt; }
        __syncthreads();
        if (bci >= KTOP) lo = mid; else hi = mid - 1;
    }
    const unsigned kth = lo;

    // ---- count strictly-greater ----
    int cg = 0;
#pragma unroll
    for (int j = 0; j < 8; j++) cg += (__float_as_uint(a[j]) > kth);
#pragma unroll
    for (int o = 16; o; o >>= 1) cg += __shfl_xor_sync(0xffffffffu, cg, o);
    if (lane == 0) shi[w] = cg;
    __syncthreads();
    if (t == 0) { int tt = 0;
#pragma unroll
        for (int i = 0; i < 8; i++) tt += shi[i];
        bci = tt; }
    __syncthreads();
    const int rem = KTOP - bci;   // how many ties to keep (lowest index first)

    // ---- index-ordered rank among ties (thread-contiguous layout) ----
    int eq = 0;
#pragma unroll
    for (int j = 0; j < 8; j++) eq += (__float_as_uint(a[j]) == kth);
    int v = eq;
#pragma unroll
    for (int o = 1; o < 32; o <<= 1) {
        int tv = __shfl_up_sync(0xffffffffu, v, o);
        if (lane >= o) v += tv;
    }
    if (lane == 31) shi[w] = v;
    __syncthreads();
    int off = 0;
    for (int i = 0; i < w; i++) off += shi[i];
    int excl = off + v - eq;

    int seen = 0;
#pragma unroll
    for (int j = 0; j < 8; j++) {
        unsigned bj = __float_as_uint(a[j]);
        bool keep = (bj > kth) || (bj == kth && (excl + seen) < rem);
        if (bj == kth) seen++;
        if (!keep) a[j] = 0.0f;
    }

    *(float4*)(row + t * 8)     = *(float4*)(a);
    *(float4*)(row + t * 8 + 4) = *(float4*)(a + 4);
}

// =====================================================================
// AV GEMM: ctx[z] = attn[z](2048x2048) @ v[z](2048x64); merged-head out.
// Tile 128(M) x 64(N), K-tile 32, register-prefetched single smem buffer.
// =====================================================================
__global__ __launch_bounds__(256, 2)
void gemm_av_kernel(const float* __restrict__ Abase,
                    const float* __restrict__ Vbase,
                    float* __restrict__ C)
{
    __shared__ float As[32][128];
    __shared__ float Bs[32][64];
    const int z = blockIdx.z;
    const int b = z >> 3, h = z & 7;
    const float* A  = Abase + (size_t)z * LQ_ * LK_;
    const float* Bv = Vbase + (size_t)z * LK_ * DH_;
    const int m0 = blockIdx.y * 128;
    const int t  = threadIdx.x;

    const int arow = t >> 1, ac = (t & 1) * 16;
    const float* Ald = A + (size_t)(m0 + arow) * LK_ + ac;
    const int brow = t >> 3, bc = (t & 7) * 8;
    const float* Bld = Bv + (size_t)brow * DH_ + bc;

    const int tm = (t >> 4) * 8, tn = (t & 15) * 4;

    float acc[8][4];
#pragma unroll
    for (int i = 0; i < 8; i++)
#pragma unroll
        for (int j = 0; j < 4; j++) acc[i][j] = 0.0f;

    float4 ar[4], br[2];
    ar[0] = *(const float4*)(Ald + 0);
    ar[1] = *(const float4*)(Ald + 4);
    ar[2] = *(const float4*)(Ald + 8);
    ar[3] = *(const float4*)(Ald + 12);
    br[0] = *(const float4*)(Bld + 0);
    br[1] = *(const float4*)(Bld + 4);

    const int NT = LK_ / 32;   // 64
    for (int kt = 0; kt < NT; kt++) {
        __syncthreads();
#pragma unroll
        for (int i = 0; i < 4; i++) {
            As[ac + 4*i + 0][arow] = ar[i].x;
            As[ac + 4*i + 1][arow] = ar[i].y;
            As[ac + 4*i + 2][arow] = ar[i].z;
            As[ac + 4*i + 3][arow] = ar[i].w;
        }
        *(float4*)&Bs[brow][bc]     = br[0];
        *(float4*)&Bs[brow][bc + 4] = br[1];
        __syncthreads();
        if (kt + 1 < NT) {
            const float* An = Ald + (kt + 1) * 32;
            ar[0] = *(const float4*)(An + 0);
            ar[1] = *(const float4*)(An + 4);
            ar[2] = *(const float4*)(An + 8);
            ar[3] = *(const float4*)(An + 12);
            const float* Bn = Bld + (size_t)(kt + 1) * 32 * DH_;
            br[0] = *(const float4*)(Bn + 0);
            br[1] = *(const float4*)(Bn + 4);
        }
#pragma unroll 8
        for (int kc = 0; kc < 32; kc++) {
            float a[8], bb[4];
            *(float4*)(a)     = *(const float4*)&As[kc][tm];
            *(float4*)(a + 4) = *(const float4*)&As[kc][tm + 4];
            *(float4*)(bb)    = *(const float4*)&Bs[kc][tn];
#pragma unroll
            for (int i = 0; i < 8; i++)
#pragma unroll
                for (int j = 0; j < 4; j++)
                    acc[i][j] = fmaf(a[i], bb[j], acc[i][j]);
        }
    }

#pragma unroll
    for (int i = 0; i < 8; i++) {
        const int mm = m0 + tm + i;
        float4 o;
        o.x = acc[i][0]; o.y = acc[i][1]; o.z = acc[i][2]; o.w = acc[i][3];
        *(float4*)(C + ((size_t)(b * LQ_ + mm) * D_ + h * DH_ + tn)) = o;
    }
}

// =====================================================================
// host launcher
// =====================================================================
extern "C" void kernel_launch(void* const* d_in, const int* in_sizes, int n_in,
                              void* d_out, int out_size)
{
    (void)in_sizes; (void)n_in; (void)out_size;
    const float* q_in = (const float*)d_in[0];
    const float* k_in = (const float*)d_in[1];
    const float* v_in = (const float*)d_in[2];
    const float* Wq   = (const float*)d_in[3];
    const float* bq   = (const float*)d_in[4];
    const float* Wk   = (const float*)d_in[5];
    const float* bk   = (const float*)d_in[6];
    const float* Wv   = (const float*)d_in[7];
    const float* bv   = (const float*)d_in[8];
    const float* Wo   = (const float*)d_in[9];
    const float* bo   = (const float*)d_in[10];
    float* out = (float*)d_out;

    float *qn, *kn, *vv, *sc, *ctx;
    cudaGetSymbolAddress((void**)&qn,  g_qn);
    cudaGetSymbolAddress((void**)&kn,  g_kn);
    cudaGetSymbolAddress((void**)&vv,  g_vv);
    cudaGetSymbolAddress((void**)&sc,  g_sc);
    cudaGetSymbolAddress((void**)&ctx, g_ctx);

    const int M = B_ * LQ_;   // 8192

    // 1-3. projections (q, k, v+tanh) -> [b,h,l,e]
    dim3 gproj(D_ / 128, M / 128, 1);
    gemm_bt_kernel<0><<<gproj, 256>>>(q_in, Wq, bq, qn, M, D_, D_, D_, D_, 0, 0, 0, 0, 0.0f);
    gemm_bt_kernel<0><<<gproj, 256>>>(k_in, Wk, bk, kn, M, D_, D_, D_, D_, 0, 0, 0, 0, 0.0f);
    gemm_bt_kernel<0><<<gproj, 256>>>(v_in, Wv, bv, vv, M, D_, D_, D_, D_, 0, 0, 0, 1, 0.0f);

    // 4-5. qk-norm
    const int nrows = B_ * H_ * LQ_;   // 65536
    l2norm_kernel<<<nrows / 8, 256>>>(qn, nrows);
    l2norm_kernel<<<nrows / 8, 256>>>(kn, nrows);

    // 6. logits (batched over b*h), scale = 1/sqrt(64)
    dim3 glog(LK_ / 128, LQ_ / 128, B_ * H_);
    gemm_bt_kernel<1><<<glog, 256>>>(qn, kn, nullptr, sc,
                                     LQ_, LK_, DH_, DH_, DH_,
                                     (size_t)LQ_ * DH_, (size_t)LK_ * DH_,
                                     (size_t)LQ_ * LK_, 0, 0.125f);

    // 7. softmax + smoothing + gate + exact top-k mask (in place)
    softmax_topk_kernel<<<B_ * H_ * LQ_, 256>>>(sc);

    // 8. AV -> merged heads
    dim3 gav(1, LQ_ / 128, B_ * H_);
    gemm_av_kernel<<<gav, 256>>>(sc, vv, ctx);

    // 9. output projection + bias -> d_out
    gemm_bt_kernel<2><<<gproj, 256>>>(ctx, Wo, bo, out, M, D_, D_, D_, D_, 0, 0, 0, 0, 0.0f);
}

// round 4
// speedup vs baseline: 1.1789x; 1.1789x over previous
#include <cuda_runtime.h>
#include <cuda_bf16.h>
#include <math.h>
#include <stdint.h>

// ---------------- problem constants ----------------
#define B_    4
#define H_    8
#define LQ_   2048
#define LK_   2048
#define DH_   64
#define D_    512
#define KTOP  205

// ---------------- device scratch (no allocations allowed) ----------------
__device__ float          g_qn [(size_t)B_ * H_ * LQ_ * DH_];   // 16 MB
__device__ float          g_kn [(size_t)B_ * H_ * LK_ * DH_];   // 16 MB
__device__ __nv_bfloat16  g_vb [(size_t)B_ * H_ * LK_ * DH_];   // 8 MB, v [z][l][e] bf16
__device__ float          g_sc [(size_t)B_ * H_ * LQ_ * LK_];   // 512 MB fp32 scores
__device__ __nv_bfloat16  g_ab [(size_t)B_ * H_ * LQ_ * LK_];   // 256 MB bf16 attn
__device__ float          g_ctx[(size_t)B_ * LQ_ * D_];         // 16 MB

// ---------------- accurate expf, fast-math-proof (~1 ulp) ----------------
__device__ __forceinline__ float exp_rn(float x) {
    if (x < -87.0f) return 0.0f;
    float n = rintf(__fmul_rn(x, 1.4426950408889634f));
    float f = __fmaf_rn(-n, 0.6931471824645996f, x);
    f = __fmaf_rn(-n, -1.9046543e-09f, f);
    float p = 1.9841269841e-04f;
    p = __fmaf_rn(p, f, 1.3888888889e-03f);
    p = __fmaf_rn(p, f, 8.3333333333e-03f);
    p = __fmaf_rn(p, f, 4.1666666667e-02f);
    p = __fmaf_rn(p, f, 1.6666666667e-01f);
    p = __fmaf_rn(p, f, 0.5f);
    p = __fmaf_rn(p, f, 1.0f);
    p = __fmaf_rn(p, f, 1.0f);
    return ldexpf(p, (int)n);
}

// =====================================================================
// GEMM: C = A(MxK) * Bt(NxK)^T, 128x128 tile, K-chunk 8, 8x8 microtile.
// EPI 0: q/k projection -> [b,h,l,e] fp32 (+bias)
// EPI 1: scores         -> C[m*N+n] = acc * scale
// EPI 2: out-proj       -> C[m*N+n] = acc + bias[n]
// EPI 3: v projection   -> tanh(acc+bias) as bf16 into v [b,h,l,e]
// =====================================================================
template<int EPI>
__global__ __launch_bounds__(256, 2)
void gemm_bt_kernel(const float* __restrict__ A, const float* __restrict__ Bt,
                    const float* __restrict__ bias, float* __restrict__ C,
                    int M, int N, int K, int lda, int ldb,
                    size_t strideA, size_t strideB, size_t strideC, float scale)
{
    __shared__ float As[2][8][128];
    __shared__ float Bs[2][8][128];
    const int z = blockIdx.z;
    A  += strideA * (size_t)z;
    Bt += strideB * (size_t)z;
    C  += strideC * (size_t)z;

    const int m0 = blockIdx.y * 128;
    const int n0 = blockIdx.x * 128;
    const int t  = threadIdx.x;

    const int lrow = t >> 1;
    const int lcol = (t & 1) << 2;
    const float* Ald = A  + (size_t)(m0 + lrow) * lda + lcol;
    const float* Bld = Bt + (size_t)(n0 + lrow) * ldb + lcol;

    const int mi = (t >> 4) << 3;
    const int ni = (t & 15) << 3;

    float acc[8][8];
#pragma unroll
    for (int i = 0; i < 8; i++)
#pragma unroll
        for (int j = 0; j < 8; j++) acc[i][j] = 0.0f;

    float4 av = *(const float4*)Ald;
    float4 bv = *(const float4*)Bld;
    As[0][lcol+0][lrow]=av.x; As[0][lcol+1][lrow]=av.y; As[0][lcol+2][lrow]=av.z; As[0][lcol+3][lrow]=av.w;
    Bs[0][lcol+0][lrow]=bv.x; Bs[0][lcol+1][lrow]=bv.y; Bs[0][lcol+2][lrow]=bv.z; Bs[0][lcol+3][lrow]=bv.w;
    __syncthreads();

    const int nc = K >> 3;
    for (int c = 0; c < nc; ++c) {
        const int cur = c & 1;
        if (c + 1 < nc) {
            av = *(const float4*)(Ald + (c + 1) * 8);
            bv = *(const float4*)(Bld + (c + 1) * 8);
        }
#pragma unroll
        for (int kc = 0; kc < 8; ++kc) {
            float a[8], b[8];
            *(float4*)(a)     = *(const float4*)&As[cur][kc][mi];
            *(float4*)(a + 4) = *(const float4*)&As[cur][kc][mi + 4];
            *(float4*)(b)     = *(const float4*)&Bs[cur][kc][ni];
            *(float4*)(b + 4) = *(const float4*)&Bs[cur][kc][ni + 4];
#pragma unroll
            for (int i = 0; i < 8; i++)
#pragma unroll
                for (int j = 0; j < 8; j++)
                    acc[i][j] = fmaf(a[i], b[j], acc[i][j]);
        }
        if (c + 1 < nc) {
            const int nxt = cur ^ 1;
            As[nxt][lcol+0][lrow]=av.x; As[nxt][lcol+1][lrow]=av.y; As[nxt][lcol+2][lrow]=av.z; As[nxt][lcol+3][lrow]=av.w;
            Bs[nxt][lcol+0][lrow]=bv.x; Bs[nxt][lcol+1][lrow]=bv.y; Bs[nxt][lcol+2][lrow]=bv.z; Bs[nxt][lcol+3][lrow]=bv.w;
            __syncthreads();
        }
    }

    if (EPI == 0) {
#pragma unroll
        for (int i = 0; i < 8; i++) {
            const int m  = m0 + mi + i;
            const int bb = m >> 11;
            const int l  = m & (LQ_ - 1);
#pragma unroll
            for (int jj = 0; jj < 8; jj += 4) {
                const int n = n0 + ni + jj;
                const int h = n >> 6, e = n & 63;
                float4 o;
                o.x = acc[i][jj+0] + bias[n+0];
                o.y = acc[i][jj+1] + bias[n+1];
                o.z = acc[i][jj+2] + bias[n+2];
                o.w = acc[i][jj+3] + bias[n+3];
                const size_t off = (((size_t)(bb * H_ + h)) * LQ_ + l) * DH_ + e;
                *(float4*)(C + off) = o;
            }
        }
    } else if (EPI == 1) {
#pragma unroll
        for (int i = 0; i < 8; i++) {
            const size_t rb = (size_t)(m0 + mi + i) * N + n0 + ni;
#pragma unroll
            for (int jj = 0; jj < 8; jj += 4) {
                float4 o;
                o.x = acc[i][jj+0] * scale;
                o.y = acc[i][jj+1] * scale;
                o.z = acc[i][jj+2] * scale;
                o.w = acc[i][jj+3] * scale;
                *(float4*)(C + rb + jj) = o;
            }
        }
    } else if (EPI == 2) {
#pragma unroll
        for (int i = 0; i < 8; i++) {
            const size_t rb = (size_t)(m0 + mi + i) * N + n0 + ni;
#pragma unroll
            for (int jj = 0; jj < 8; jj += 4) {
                const int n = n0 + ni + jj;
                float4 o;
                o.x = acc[i][jj+0] + bias[n+0];
                o.y = acc[i][jj+1] + bias[n+1];
                o.z = acc[i][jj+2] + bias[n+2];
                o.w = acc[i][jj+3] + bias[n+3];
                *(float4*)(C + rb + jj) = o;
            }
        }
    } else {  // EPI == 3: v projection -> tanh -> bf16 v [b,h,l,e]
        __nv_bfloat16* VB = (__nv_bfloat16*)C;
#pragma unroll
        for (int i = 0; i < 8; i++) {
            const int m  = m0 + mi + i;
            const int bb = m >> 11;
            const int l  = m & (LQ_ - 1);
#pragma unroll
            for (int j = 0; j < 8; j++) {
                const int n = n0 + ni + j;
                const int h = n >> 6, e = n & 63;
                float ov = tanhf(acc[i][j] + bias[n]);
                VB[(((size_t)(bb * H_ + h)) * LK_ + l) * DH_ + e] = __float2bfloat16(ov);
            }
        }
    }
}

// ---------------- L2 normalize rows of 64 (warp per row) ----------------
__global__ __launch_bounds__(256)
void l2norm_kernel(float* __restrict__ X, int nrows)
{
    const int gw   = (blockIdx.x * blockDim.x + threadIdx.x) >> 5;
    const int lane = threadIdx.x & 31;
    if (gw >= nrows) return;
    float* r = X + (size_t)gw * DH_;
    float a = r[lane], b = r[lane + 32];
    float s = __fmaf_rn(a, a, __fmul_rn(b, b));
#pragma unroll
    for (int o = 16; o; o >>= 1) s += __shfl_xor_sync(0xffffffffu, s, o);
    float n = fmaxf(__fsqrt_rn(s), 1e-12f);
    r[lane]      = __fdiv_rn(a, n);
    r[lane + 32] = __fdiv_rn(b, n);
}

// =====================================================================
// Per-row: softmax -> smoothing -> gate -> exact top-205 mask -> bf16 out.
// Block of 256 threads per row; thread t owns elements [t*8, t*8+8).
// =====================================================================
__global__ __launch_bounds__(256)
void softmax_topk_kernel(const float* __restrict__ S, __nv_bfloat16* __restrict__ AB)
{
    __shared__ float shf[8];
    __shared__ int   shi2[2][8];
    __shared__ float bcf;

    const int t    = threadIdx.x;
    const int lane = t & 31;
    const int w    = t >> 5;
    const float* row = S + (size_t)blockIdx.x * LK_;

    float x[8];
    *(float4*)(x)     = *(const float4*)(row + t * 8);
    *(float4*)(x + 4) = *(const float4*)(row + t * 8 + 4);

    // row max
    float m = x[0];
#pragma unroll
    for (int j = 1; j < 8; j++) m = fmaxf(m, x[j]);
#pragma unroll
    for (int o = 16; o; o >>= 1) m = fmaxf(m, __shfl_xor_sync(0xffffffffu, m, o));
    if (lane == 0) shf[w] = m;
    __syncthreads();
    if (t == 0) { float mm = shf[0];
#pragma unroll
        for (int i = 1; i < 8; i++) mm = fmaxf(mm, shf[i]);
        bcf = mm; }
    __syncthreads();
    m = bcf;

    // exp + sum
    float e[8]; float s = 0.0f;
#pragma unroll
    for (int j = 0; j < 8; j++) { e[j] = exp_rn(__fadd_rn(x[j], -m)); s = __fadd_rn(s, e[j]); }
#pragma unroll
    for (int o = 16; o; o >>= 1) s += __shfl_xor_sync(0xffffffffu, s, o);
    if (lane == 0) shf[w] = s;
    __syncthreads();
    if (t == 0) { float ss = 0.0f;
#pragma unroll
        for (int i = 0; i < 8; i++) ss = __fadd_rn(ss, shf[i]);
        bcf = ss; }
    __syncthreads();
    s = bcf;

    // smoothing + gate (exact single-rounding ops)
    const float SMC = 4.8828125e-06f;   // (float)(0.01/2048)
    float a[8]; unsigned ab[8];
#pragma unroll
    for (int j = 0; j < 8; j++) {
        float p = __fdiv_rn(e[j], s);
        float q = __fadd_rn(__fmul_rn(0.99f, p), SMC);
        a[j]  = (q >= 1e-4f) ? q : 0.0f;
        ab[j] = __float_as_uint(a[j]);
    }

    int sel = 0;
    auto bsum = [&](int c) -> int {
        c = __reduce_add_sync(0xffffffffu, c);
        if (lane == 0) shi2[sel][w] = c;
        __syncthreads();
        int s2 = 0;
#pragma unroll
        for (int i = 0; i < 8; i++) s2 += shi2[sel][i];
        sel ^= 1;
        return s2;
    };

    const unsigned BLO = __float_as_uint(1e-4f);
    int cnt = 0;
#pragma unroll
    for (int j = 0; j < 8; j++) cnt += (ab[j] >= BLO);
    const int c0 = bsum(cnt);

    unsigned kth = 0u;
    if (c0 >= KTOP) {
        unsigned lo = BLO, hi = __float_as_uint(1.0f);
        while (lo < hi) {
            unsigned mid = lo + ((hi - lo + 1) >> 1);
            int c = 0;
#pragma unroll
            for (int j = 0; j < 8; j++) c += (ab[j] >= mid);
            if (bsum(c) >= KTOP) lo = mid; else hi = mid - 1;
        }
        kth = lo;
    }

    int cg = 0;
#pragma unroll
    for (int j = 0; j < 8; j++) cg += (ab[j] > kth);
    cg = bsum(cg);
    const int rem = KTOP - cg;

    // index-ordered rank among ties
    int eq = 0;
#pragma unroll
    for (int j = 0; j < 8; j++) eq += (ab[j] == kth);
    int v = eq;
#pragma unroll
    for (int o = 1; o < 32; o <<= 1) {
        int tv = __shfl_up_sync(0xffffffffu, v, o);
        if (lane >= o) v += tv;
    }
    if (lane == 31) shi2[sel][w] = v;
    __syncthreads();
    int off = 0;
    for (int i = 0; i < w; i++) off += shi2[sel][i];
    const int excl = off + v - eq;

    int seen = 0;
#pragma unroll
    for (int j = 0; j < 8; j++) {
        bool keep = (ab[j] > kth) || (ab[j] == kth && (excl + seen) < rem);
        if (ab[j] == kth) seen++;
        if (!keep) a[j] = 0.0f;
    }

    // pack to bf16 and store
    __nv_bfloat162 h0 = __floats2bfloat162_rn(a[0], a[1]);
    __nv_bfloat162 h1 = __floats2bfloat162_rn(a[2], a[3]);
    __nv_bfloat162 h2 = __floats2bfloat162_rn(a[4], a[5]);
    __nv_bfloat162 h3 = __floats2bfloat162_rn(a[6], a[7]);
    uint4 o;
    o.x = ((uint32_t)__bfloat16_as_ushort(h0.y) << 16) | __bfloat16_as_ushort(h0.x);
    o.y = ((uint32_t)__bfloat16_as_ushort(h1.y) << 16) | __bfloat16_as_ushort(h1.x);
    o.z = ((uint32_t)__bfloat16_as_ushort(h2.y) << 16) | __bfloat16_as_ushort(h2.x);
    o.w = ((uint32_t)__bfloat16_as_ushort(h3.y) << 16) | __bfloat16_as_ushort(h3.x);
    *(uint4*)(AB + (size_t)blockIdx.x * LK_ + t * 8) = o;
}

// =====================================================================
// AV via mma.sync bf16 HMMA (arch-agnostic PTX; tcgen05 is unavailable
// because the harness emits compute_103 PTX, not compute_103a).
// ctx[z](2048x64) = attn[z](2048x2048 bf16) @ v[z](2048x64 bf16).
// Block: 8 warps -> 128 q-rows x 64 cols; K double-buffered in 64-chunks.
// =====================================================================
__device__ __forceinline__ uint32_t smem_u32(const void* p) {
    uint32_t a;
    asm("{ .reg .u64 t; cvta.to.shared.u64 t, %1; cvt.u32.u64 %0, t; }" : "=r"(a) : "l"(p));
    return a;
}
__device__ __forceinline__ uint32_t swz128(uint32_t o) { return o ^ ((o >> 3) & 0x70); }

__global__ __launch_bounds__(256, 4)
void av_hmma_kernel(const __nv_bfloat16* __restrict__ attn,
                    const __nv_bfloat16* __restrict__ vb,
                    float* __restrict__ ctx)
{
    // buffer p: A tile [128 rows x 128B] at p*24576, B tile [64 rows x 128B] at p*24576+16384
    __shared__ char sm[2 * 24576];
    const uint32_t sb = smem_u32(sm);

    const int t    = threadIdx.x;
    const int lane = t & 31;
    const int w    = t >> 5;
    const int z    = blockIdx.z;
    const int m0   = blockIdx.y * 128;
    const int bb   = z >> 3, hh = z & 7;

    const char* Ag = (const char*)(attn + ((size_t)z * LQ_ + m0) * LK_);
    const char* Vg = (const char*)(vb + (size_t)z * LK_ * DH_);

    // global->smem assignments (bytes)
    const int ar = t >> 1, ah = t & 1;     // A: row, 64B-half ; chunk c at byte c*128 in row
    const int br = t >> 2, bq = t & 3;     // B: row, 32B-quarter ; chunk c at row c*64

    float acc[8][4];
#pragma unroll
    for (int i = 0; i < 8; i++)
#pragma unroll
        for (int j = 0; j < 4; j++) acc[i][j] = 0.0f;

    uint4 apre[4]; uint4 bpre[2];
    auto prefetch = [&](int c) {
        const char* a = Ag + (size_t)ar * (LK_ * 2) + c * 128 + ah * 64;
#pragma unroll
        for (int i = 0; i < 4; i++) apre[i] = *(const uint4*)(a + i * 16);
        const char* b = Vg + (size_t)(c * 64 + br) * (DH_ * 2) + bq * 32;
#pragma unroll
        for (int i = 0; i < 2; i++) bpre[i] = *(const uint4*)(b + i * 16);
    };
    auto store_sm = [&](int p) {
        char* base = sm + p * 24576;
#pragma unroll
        for (int i = 0; i < 4; i++)
            *(uint4*)(base + swz128((uint32_t)(ar * 128 + ah * 64 + i * 16))) = apre[i];
#pragma unroll
        for (int i = 0; i < 2; i++)
            *(uint4*)(base + 16384 + swz128((uint32_t)(br * 128 + bq * 32 + i * 16))) = bpre[i];
    };

    // per-lane ldmatrix address components
    const int lm = lane >> 3, lr = lane & 7;
    const uint32_t a_row  = (uint32_t)(w * 16 + (lm & 1) * 8 + lr);
    const uint32_t a_colp = (uint32_t)((lm >> 1) * 16);
    const uint32_t b_rowp = (uint32_t)((lm & 1) * 8 + lr);
    const uint32_t b_colp = (uint32_t)((lm >> 1) * 16);

    prefetch(0); store_sm(0);
    prefetch(1);
    __syncthreads();

    for (int c = 0; c < 32; c++) {
        const int p = c & 1;
        if (c < 31) store_sm(p ^ 1);
        if (c < 30) prefetch(c + 2);

        const uint32_t abase = sb + p * 24576;
        const uint32_t bbase = abase + 16384;
#pragma unroll
        for (int ks = 0; ks < 4; ks++) {
            uint32_t a0, a1, a2, a3;
            {
                uint32_t addr = abase + swz128(a_row * 128 + ks * 32 + a_colp);
                asm volatile("ldmatrix.sync.aligned.m8n8.x4.shared.b16 {%0,%1,%2,%3}, [%4];"
                             : "=r"(a0), "=r"(a1), "=r"(a2), "=r"(a3) : "r"(addr));
            }
#pragma unroll
            for (int np = 0; np < 4; np++) {
                uint32_t b0, b1, b2, b3;
                uint32_t addr = bbase + swz128((ks * 16 + b_rowp) * 128 + np * 32 + b_colp);
                asm volatile("ldmatrix.sync.aligned.m8n8.x4.trans.shared.b16 {%0,%1,%2,%3}, [%4];"
                             : "=r"(b0), "=r"(b1), "=r"(b2), "=r"(b3) : "r"(addr));
                asm volatile("mma.sync.aligned.m16n8k16.row.col.f32.bf16.bf16.f32 "
                             "{%0,%1,%2,%3}, {%4,%5,%6,%7}, {%8,%9}, {%0,%1,%2,%3};"
                             : "+f"(acc[2*np][0]), "+f"(acc[2*np][1]), "+f"(acc[2*np][2]), "+f"(acc[2*np][3])
                             : "r"(a0), "r"(a1), "r"(a2), "r"(a3), "r"(b0), "r"(b1));
                asm volatile("mma.sync.aligned.m16n8k16.row.col.f32.bf16.bf16.f32 "
                             "{%0,%1,%2,%3}, {%4,%5,%6,%7}, {%8,%9}, {%0,%1,%2,%3};"
                             : "+f"(acc[2*np+1][0]), "+f"(acc[2*np+1][1]), "+f"(acc[2*np+1][2]), "+f"(acc[2*np+1][3])
                             : "r"(a0), "r"(a1), "r"(a2), "r"(a3), "r"(b2), "r"(b3));
            }
        }
        __syncthreads();
    }

    // epilogue: C frag m16n8 -> ctx fp32 [b*2048+m][h*64+n]
    const int r0 = lane >> 2, c0 = (lane & 3) * 2;
    const int mrow = m0 + w * 16 + r0;
    float* dst0 = ctx + (size_t)(bb * LQ_ + mrow) * D_ + hh * DH_ + c0;
    float* dst1 = dst0 + 8 * D_;
#pragma unroll
    for (int nt = 0; nt < 8; nt++) {
        *(float2*)(dst0 + nt * 8) = make_float2(acc[nt][0], acc[nt][1]);
        *(float2*)(dst1 + nt * 8) = make_float2(acc[nt][2], acc[nt][3]);
    }
}

// =====================================================================
// host launcher
// =====================================================================
extern "C" void kernel_launch(void* const* d_in, const int* in_sizes, int n_in,
                              void* d_out, int out_size)
{
    (void)in_sizes; (void)n_in; (void)out_size;
    const float* q_in = (const float*)d_in[0];
    const float* k_in = (const float*)d_in[1];
    const float* v_in = (const float*)d_in[2];
    const float* Wq   = (const float*)d_in[3];
    const float* bq   = (const float*)d_in[4];
    const float* Wk   = (const float*)d_in[5];
    const float* bk   = (const float*)d_in[6];
    const float* Wv   = (const float*)d_in[7];
    const float* bv   = (const float*)d_in[8];
    const float* Wo   = (const float*)d_in[9];
    const float* bo   = (const float*)d_in[10];
    float* out = (float*)d_out;

    float *qn, *kn, *sc, *ctx;
    __nv_bfloat16 *vb, *ab;
    cudaGetSymbolAddress((void**)&qn,  g_qn);
    cudaGetSymbolAddress((void**)&kn,  g_kn);
    cudaGetSymbolAddress((void**)&vb,  g_vb);
    cudaGetSymbolAddress((void**)&sc,  g_sc);
    cudaGetSymbolAddress((void**)&ab,  g_ab);
    cudaGetSymbolAddress((void**)&ctx, g_ctx);

    const int M = B_ * LQ_;   // 8192

    // 1-3. projections: q,k -> fp32 [b,h,l,e]; v -> tanh -> bf16 [b,h,l,e]
    dim3 gproj(D_ / 128, M / 128, 1);
    gemm_bt_kernel<0><<<gproj, 256>>>(q_in, Wq, bq, qn, M, D_, D_, D_, D_, 0, 0, 0, 0.0f);
    gemm_bt_kernel<0><<<gproj, 256>>>(k_in, Wk, bk, kn, M, D_, D_, D_, D_, 0, 0, 0, 0.0f);
    gemm_bt_kernel<3><<<gproj, 256>>>(v_in, Wv, bv, (float*)vb, M, D_, D_, D_, D_, 0, 0, 0, 0.0f);

    // 4-5. qk-norm
    const int nrows = B_ * H_ * LQ_;
    l2norm_kernel<<<nrows / 8, 256>>>(qn, nrows);
    l2norm_kernel<<<nrows / 8, 256>>>(kn, nrows);

    // 6. logits (batched over b*h), scale = 1/sqrt(64)
    dim3 glog(LK_ / 128, LQ_ / 128, B_ * H_);
    gemm_bt_kernel<1><<<glog, 256>>>(qn, kn, nullptr, sc,
                                     LQ_, LK_, DH_, DH_, DH_,
                                     (size_t)LQ_ * DH_, (size_t)LK_ * DH_,
                                     (size_t)LQ_ * LK_, 0.125f);

    // 7. softmax + smoothing + gate + exact top-k -> bf16 attn
    softmax_topk_kernel<<<B_ * H_ * LQ_, 256>>>(sc, ab);

    // 8. AV on tensor cores (mma.sync bf16) -> merged-head fp32 ctx
    dim3 gav(1, LQ_ / 128, B_ * H_);
    av_hmma_kernel<<<gav, 256>>>(ab, vb, ctx);

    // 9. output projection + bias -> d_out
    gemm_bt_kernel<2><<<gproj, 256>>>(ctx, Wo, bo, out, M, D_, D_, D_, D_, 0, 0, 0, 0.0f);
}

// round 5
// speedup vs baseline: 1.2887x; 1.0931x over previous
#include <cuda_runtime.h>
#include <cuda_bf16.h>
#include <cuda_fp16.h>
#include <math.h>
#include <stdint.h>

// ---------------- problem constants ----------------
#define B_    4
#define H_    8
#define LQ_   2048
#define LK_   2048
#define DH_   64
#define D_    512
#define KTOP  205

// ---------------- device scratch (no allocations allowed) ----------------
__device__ float          g_qn [(size_t)B_ * H_ * LQ_ * DH_];   // 16 MB fp32 q proj
__device__ float          g_kn [(size_t)B_ * H_ * LK_ * DH_];   // 16 MB fp32 k proj
__device__ __half         g_qh [(size_t)B_ * H_ * LQ_ * DH_];   // 8 MB
__device__ __half         g_ql [(size_t)B_ * H_ * LQ_ * DH_];   // 8 MB
__device__ __half         g_kh [(size_t)B_ * H_ * LK_ * DH_];   // 8 MB
__device__ __half         g_kl [(size_t)B_ * H_ * LK_ * DH_];   // 8 MB
__device__ __nv_bfloat16  g_vb [(size_t)B_ * H_ * LK_ * DH_];   // 8 MB, v [z][l][e] bf16
__device__ float          g_sc [(size_t)B_ * H_ * LQ_ * LK_];   // 512 MB fp32 scores
__device__ __nv_bfloat16  g_ab [(size_t)B_ * H_ * LQ_ * LK_];   // 256 MB bf16 attn
__device__ float          g_ctx[(size_t)B_ * LQ_ * D_];         // 16 MB

// ---------------- helpers ----------------
__device__ __forceinline__ uint32_t smem_u32(const void* p) {
    uint32_t a;
    asm("{ .reg .u64 t; cvta.to.shared.u64 t, %1; cvt.u32.u64 %0, t; }" : "=r"(a) : "l"(p));
    return a;
}
__device__ __forceinline__ uint32_t swz128(uint32_t o) { return o ^ ((o >> 3) & 0x70); }

// accurate expf, fast-math-proof (~1 ulp)
__device__ __forceinline__ float exp_rn(float x) {
    if (x < -87.0f) return 0.0f;
    float n = rintf(__fmul_rn(x, 1.4426950408889634f));
    float f = __fmaf_rn(-n, 0.6931471824645996f, x);
    f = __fmaf_rn(-n, -1.9046543e-09f, f);
    float p = 1.9841269841e-04f;
    p = __fmaf_rn(p, f, 1.3888888889e-03f);
    p = __fmaf_rn(p, f, 8.3333333333e-03f);
    p = __fmaf_rn(p, f, 4.1666666667e-02f);
    p = __fmaf_rn(p, f, 1.6666666667e-01f);
    p = __fmaf_rn(p, f, 0.5f);
    p = __fmaf_rn(p, f, 1.0f);
    p = __fmaf_rn(p, f, 1.0f);
    return ldexpf(p, (int)n);
}

// =====================================================================
// fp32 SIMT GEMM: C = A(MxK) * Bt(NxK)^T, 128x128 tile.
// EPI 0: q/k projection -> [b,h,l,e] fp32 (+bias)
// EPI 2: out-proj       -> C[m*N+n] = acc + bias[n]
// EPI 3: v projection   -> tanh(acc+bias) as bf16 into v [b,h,l,e]
// =====================================================================
template<int EPI>
__global__ __launch_bounds__(256, 2)
void gemm_bt_kernel(const float* __restrict__ A, const float* __restrict__ Bt,
                    const float* __restrict__ bias, float* __restrict__ C,
                    int M, int N, int K, int lda, int ldb)
{
    __shared__ float As[2][8][128];
    __shared__ float Bs[2][8][128];
    const int m0 = blockIdx.y * 128;
    const int n0 = blockIdx.x * 128;
    const int t  = threadIdx.x;

    const int lrow = t >> 1;
    const int lcol = (t & 1) << 2;
    const float* Ald = A  + (size_t)(m0 + lrow) * lda + lcol;
    const float* Bld = Bt + (size_t)(n0 + lrow) * ldb + lcol;

    const int mi = (t >> 4) << 3;
    const int ni = (t & 15) << 3;

    float acc[8][8];
#pragma unroll
    for (int i = 0; i < 8; i++)
#pragma unroll
        for (int j = 0; j < 8; j++) acc[i][j] = 0.0f;

    float4 av = *(const float4*)Ald;
    float4 bv = *(const float4*)Bld;
    As[0][lcol+0][lrow]=av.x; As[0][lcol+1][lrow]=av.y; As[0][lcol+2][lrow]=av.z; As[0][lcol+3][lrow]=av.w;
    Bs[0][lcol+0][lrow]=bv.x; Bs[0][lcol+1][lrow]=bv.y; Bs[0][lcol+2][lrow]=bv.z; Bs[0][lcol+3][lrow]=bv.w;
    __syncthreads();

    const int nc = K >> 3;
    for (int c = 0; c < nc; ++c) {
        const int cur = c & 1;
        if (c + 1 < nc) {
            av = *(const float4*)(Ald + (c + 1) * 8);
            bv = *(const float4*)(Bld + (c + 1) * 8);
        }
#pragma unroll
        for (int kc = 0; kc < 8; ++kc) {
            float a[8], b[8];
            *(float4*)(a)     = *(const float4*)&As[cur][kc][mi];
            *(float4*)(a + 4) = *(const float4*)&As[cur][kc][mi + 4];
            *(float4*)(b)     = *(const float4*)&Bs[cur][kc][ni];
            *(float4*)(b + 4) = *(const float4*)&Bs[cur][kc][ni + 4];
#pragma unroll
            for (int i = 0; i < 8; i++)
#pragma unroll
                for (int j = 0; j < 8; j++)
                    acc[i][j] = fmaf(a[i], b[j], acc[i][j]);
        }
        if (c + 1 < nc) {
            const int nxt = cur ^ 1;
            As[nxt][lcol+0][lrow]=av.x; As[nxt][lcol+1][lrow]=av.y; As[nxt][lcol+2][lrow]=av.z; As[nxt][lcol+3][lrow]=av.w;
            Bs[nxt][lcol+0][lrow]=bv.x; Bs[nxt][lcol+1][lrow]=bv.y; Bs[nxt][lcol+2][lrow]=bv.z; Bs[nxt][lcol+3][lrow]=bv.w;
            __syncthreads();
        }
    }

    if (EPI == 0) {
#pragma unroll
        for (int i = 0; i < 8; i++) {
            const int m  = m0 + mi + i;
            const int bb = m >> 11;
            const int l  = m & (LQ_ - 1);
#pragma unroll
            for (int jj = 0; jj < 8; jj += 4) {
                const int n = n0 + ni + jj;
                const int h = n >> 6, e = n & 63;
                float4 o;
                o.x = acc[i][jj+0] + bias[n+0];
                o.y = acc[i][jj+1] + bias[n+1];
                o.z = acc[i][jj+2] + bias[n+2];
                o.w = acc[i][jj+3] + bias[n+3];
                const size_t off = (((size_t)(bb * H_ + h)) * LQ_ + l) * DH_ + e;
                *(float4*)(C + off) = o;
            }
        }
    } else if (EPI == 2) {
#pragma unroll
        for (int i = 0; i < 8; i++) {
            const size_t rb = (size_t)(m0 + mi + i) * N + n0 + ni;
#pragma unroll
            for (int jj = 0; jj < 8; jj += 4) {
                const int n = n0 + ni + jj;
                float4 o;
                o.x = acc[i][jj+0] + bias[n+0];
                o.y = acc[i][jj+1] + bias[n+1];
                o.z = acc[i][jj+2] + bias[n+2];
                o.w = acc[i][jj+3] + bias[n+3];
                *(float4*)(C + rb + jj) = o;
            }
        }
    } else {  // EPI == 3: v projection -> tanh -> bf16 v [b,h,l,e]
        __nv_bfloat16* VB = (__nv_bfloat16*)C;
#pragma unroll
        for (int i = 0; i < 8; i++) {
            const int m  = m0 + mi + i;
            const int bb = m >> 11;
            const int l  = m & (LQ_ - 1);
#pragma unroll
            for (int j = 0; j < 8; j++) {
                const int n = n0 + ni + j;
                const int h = n >> 6, e = n & 63;
                float ov = tanhf(acc[i][j] + bias[n]);
                VB[(((size_t)(bb * H_ + h)) * LK_ + l) * DH_ + e] = __float2bfloat16(ov);
            }
        }
    }
}

// ---------------- L2 normalize + fp16 hi/lo split (warp per row) --------
// x_norm = x/||x||; hi = fp16(x_norm); lo = fp16(2048*(x_norm - hi)).
__global__ __launch_bounds__(256)
void l2norm_split_kernel(const float* __restrict__ X,
                         __half* __restrict__ Hi, __half* __restrict__ Lo,
                         int nrows)
{
    const int gw   = (blockIdx.x * blockDim.x + threadIdx.x) >> 5;
    const int lane = threadIdx.x & 31;
    if (gw >= nrows) return;
    const float* r = X + (size_t)gw * DH_;
    float2 v = *(const float2*)(r + lane * 2);
    float s = __fmaf_rn(v.x, v.x, __fmul_rn(v.y, v.y));
#pragma unroll
    for (int o = 16; o; o >>= 1) s += __shfl_xor_sync(0xffffffffu, s, o);
    float n = fmaxf(__fsqrt_rn(s), 1e-12f);
    float x0 = __fdiv_rn(v.x, n);
    float x1 = __fdiv_rn(v.y, n);
    __half h0 = __float2half_rn(x0);
    __half h1 = __float2half_rn(x1);
    __half l0 = __float2half_rn(__fmul_rn(__fadd_rn(x0, -__half2float(h0)), 2048.0f));
    __half l1 = __float2half_rn(__fmul_rn(__fadd_rn(x1, -__half2float(h1)), 2048.0f));
    ((__half2*)(Hi + (size_t)gw * DH_))[lane] = __halves2half2(h0, h1);
    ((__half2*)(Lo + (size_t)gw * DH_))[lane] = __halves2half2(l0, l1);
}

// =====================================================================
// Logits via fp16 split HMMA (fp32-exact class):
// sc[z][m][n] = 0.125 * ( qh·kh + 2^-11 * (qh·kl + ql·kh) )
// Tile: 128 q-rows x 64 k-cols, K = 64 in one shot. 8 warps, 2 CTA/SM.
// =====================================================================
__global__ __launch_bounds__(256, 2)
void logits_hmma_kernel(const __half* __restrict__ qh, const __half* __restrict__ ql,
                        const __half* __restrict__ kh, const __half* __restrict__ kl,
                        float* __restrict__ sc)
{
    __shared__ char sm[49152];   // Ah 16K | Al 16K | Bh 8K | Bl 8K
    const uint32_t sb = smem_u32(sm);
    const int t = threadIdx.x, lane = t & 31, w = t >> 5;
    const int z  = blockIdx.z;
    const int m0 = blockIdx.y * 128;
    const int n0 = blockIdx.x * 64;

    const char* Aqh = (const char*)(qh + ((size_t)z * LQ_ + m0) * DH_);
    const char* Aql = (const char*)(ql + ((size_t)z * LQ_ + m0) * DH_);
    const char* Bkh = (const char*)(kh + ((size_t)z * LK_ + n0) * DH_);
    const char* Bkl = (const char*)(kl + ((size_t)z * LK_ + n0) * DH_);

    // load A tiles: 128 rows x 128B; thread = (row t>>1, 64B half t&1)
    {
        const int r = t >> 1, hf = t & 1;
        const char* sh = Aqh + (size_t)r * 128 + hf * 64;
        const char* sl = Aql + (size_t)r * 128 + hf * 64;
#pragma unroll
        for (int i = 0; i < 4; i++) {
            uint32_t off = swz128((uint32_t)(r * 128 + hf * 64 + i * 16));
            *(uint4*)(sm + off)         = *(const uint4*)(sh + i * 16);
            *(uint4*)(sm + 16384 + off) = *(const uint4*)(sl + i * 16);
        }
    }
    // load B tiles: 64 rows x 128B; thread = (row t>>2, 32B quarter t&3)
    {
        const int r = t >> 2, qq = t & 3;
        const char* sh = Bkh + (size_t)r * 128 + qq * 32;
        const char* sl = Bkl + (size_t)r * 128 + qq * 32;
#pragma unroll
        for (int i = 0; i < 2; i++) {
            uint32_t off = swz128((uint32_t)(r * 128 + qq * 32 + i * 16));
            *(uint4*)(sm + 32768 + off) = *(const uint4*)(sh + i * 16);
            *(uint4*)(sm + 40960 + off) = *(const uint4*)(sl + i * 16);
        }
    }
    __syncthreads();

    float hh[8][4], md[8][4];
#pragma unroll
    for (int g = 0; g < 8; g++)
#pragma unroll
        for (int j = 0; j < 4; j++) { hh[g][j] = 0.0f; md[g][j] = 0.0f; }

    const int lm = lane >> 3, lr = lane & 7;
    const uint32_t a_row  = (uint32_t)(w * 16 + (lm & 1) * 8 + lr);
    const uint32_t a_colp = (uint32_t)((lm >> 1) * 16);
    const uint32_t b_rowp = (uint32_t)((lm >> 1) * 8 + lr);
    const uint32_t b_half = (uint32_t)((lm & 1) * 16);

#pragma unroll
    for (int ks = 0; ks < 4; ks++) {
        uint32_t ah0, ah1, ah2, ah3, al0, al1, al2, al3;
        {
            uint32_t ao = swz128(a_row * 128 + ks * 32 + a_colp);
            asm volatile("ldmatrix.sync.aligned.m8n8.x4.shared.b16 {%0,%1,%2,%3}, [%4];"
                         : "=r"(ah0), "=r"(ah1), "=r"(ah2), "=r"(ah3) : "r"(sb + ao));
            asm volatile("ldmatrix.sync.aligned.m8n8.x4.shared.b16 {%0,%1,%2,%3}, [%4];"
                         : "=r"(al0), "=r"(al1), "=r"(al2), "=r"(al3) : "r"(sb + 16384 + ao));
        }
#pragma unroll
        for (int np = 0; np < 4; np++) {
            uint32_t bo = swz128((np * 16 + b_rowp) * 128 + ks * 32 + b_half);
            uint32_t bh0, bh1, bh2, bh3, bl0, bl1, bl2, bl3;
            asm volatile("ldmatrix.sync.aligned.m8n8.x4.shared.b16 {%0,%1,%2,%3}, [%4];"
                         : "=r"(bh0), "=r"(bh1), "=r"(bh2), "=r"(bh3) : "r"(sb + 32768 + bo));
            asm volatile("ldmatrix.sync.aligned.m8n8.x4.shared.b16 {%0,%1,%2,%3}, [%4];"
                         : "=r"(bl0), "=r"(bl1), "=r"(bl2), "=r"(bl3) : "r"(sb + 40960 + bo));
#define MMA_F16(ACC, A0,A1,A2,A3, B0,B1) \
    asm volatile("mma.sync.aligned.m16n8k16.row.col.f32.f16.f16.f32 " \
                 "{%0,%1,%2,%3}, {%4,%5,%6,%7}, {%8,%9}, {%0,%1,%2,%3};" \
                 : "+f"((ACC)[0]), "+f"((ACC)[1]), "+f"((ACC)[2]), "+f"((ACC)[3]) \
                 : "r"(A0), "r"(A1), "r"(A2), "r"(A3), "r"(B0), "r"(B1))
            MMA_F16(hh[np*2+0], ah0,ah1,ah2,ah3, bh0,bh1);
            MMA_F16(hh[np*2+1], ah0,ah1,ah2,ah3, bh2,bh3);
            MMA_F16(md[np*2+0], ah0,ah1,ah2,ah3, bl0,bl1);
            MMA_F16(md[np*2+1], ah0,ah1,ah2,ah3, bl2,bl3);
            MMA_F16(md[np*2+0], al0,al1,al2,al3, bh0,bh1);
            MMA_F16(md[np*2+1], al0,al1,al2,al3, bh2,bh3);
#undef MMA_F16
        }
    }

    // epilogue: (hh + md/2048) * 0.125
    const float INV = 4.8828125e-04f;  // 2^-11
    const int r0 = lane >> 2, c0 = (lane & 3) * 2;
    float* base0 = sc + ((size_t)z * LQ_ + m0 + w * 16 + r0) * (size_t)LK_ + n0 + c0;
    float* base1 = base0 + 8 * (size_t)LK_;
#pragma unroll
    for (int g = 0; g < 8; g++) {
        float2 v0, v1;
        v0.x = __fmul_rn(__fmaf_rn(md[g][0], INV, hh[g][0]), 0.125f);
        v0.y = __fmul_rn(__fmaf_rn(md[g][1], INV, hh[g][1]), 0.125f);
        v1.x = __fmul_rn(__fmaf_rn(md[g][2], INV, hh[g][2]), 0.125f);
        v1.y = __fmul_rn(__fmaf_rn(md[g][3], INV, hh[g][3]), 0.125f);
        *(float2*)(base0 + g * 8) = v0;
        *(float2*)(base1 + g * 8) = v1;
    }
}

// =====================================================================
// Per-row: softmax -> smoothing -> gate -> exact top-205 mask -> bf16 out.
// =====================================================================
__global__ __launch_bounds__(256)
void softmax_topk_kernel(const float* __restrict__ S, __nv_bfloat16* __restrict__ AB)
{
    __shared__ float shf[8];
    __shared__ int   shi2[2][8];
    __shared__ float bcf;

    const int t    = threadIdx.x;
    const int lane = t & 31;
    const int w    = t >> 5;
    const float* row = S + (size_t)blockIdx.x * LK_;

    float x[8];
    *(float4*)(x)     = *(const float4*)(row + t * 8);
    *(float4*)(x + 4) = *(const float4*)(row + t * 8 + 4);

    float m = x[0];
#pragma unroll
    for (int j = 1; j < 8; j++) m = fmaxf(m, x[j]);
#pragma unroll
    for (int o = 16; o; o >>= 1) m = fmaxf(m, __shfl_xor_sync(0xffffffffu, m, o));
    if (lane == 0) shf[w] = m;
    __syncthreads();
    if (t == 0) { float mm = shf[0];
#pragma unroll
        for (int i = 1; i < 8; i++) mm = fmaxf(mm, shf[i]);
        bcf = mm; }
    __syncthreads();
    m = bcf;

    float e[8]; float s = 0.0f;
#pragma unroll
    for (int j = 0; j < 8; j++) { e[j] = exp_rn(__fadd_rn(x[j], -m)); s = __fadd_rn(s, e[j]); }
#pragma unroll
    for (int o = 16; o; o >>= 1) s += __shfl_xor_sync(0xffffffffu, s, o);
    if (lane == 0) shf[w] = s;
    __syncthreads();
    if (t == 0) { float ss = 0.0f;
#pragma unroll
        for (int i = 0; i < 8; i++) ss = __fadd_rn(ss, shf[i]);
        bcf = ss; }
    __syncthreads();
    s = bcf;

    const float SMC = 4.8828125e-06f;
    float a[8]; unsigned ab[8];
#pragma unroll
    for (int j = 0; j < 8; j++) {
        float p = __fdiv_rn(e[j], s);
        float q = __fadd_rn(__fmul_rn(0.99f, p), SMC);
        a[j]  = (q >= 1e-4f) ? q : 0.0f;
        ab[j] = __float_as_uint(a[j]);
    }

    int sel = 0;
    auto bsum = [&](int c) -> int {
        c = __reduce_add_sync(0xffffffffu, c);
        if (lane == 0) shi2[sel][w] = c;
        __syncthreads();
        int s2 = 0;
#pragma unroll
        for (int i = 0; i < 8; i++) s2 += shi2[sel][i];
        sel ^= 1;
        return s2;
    };

    const unsigned BLO = __float_as_uint(1e-4f);
    int cnt = 0;
#pragma unroll
    for (int j = 0; j < 8; j++) cnt += (ab[j] >= BLO);
    const int c0 = bsum(cnt);

    unsigned kth = 0u;
    if (c0 >= KTOP) {
        unsigned lo = BLO, hi = __float_as_uint(1.0f);
        while (lo < hi) {
            unsigned mid = lo + ((hi - lo + 1) >> 1);
            int c = 0;
#pragma unroll
            for (int j = 0; j < 8; j++) c += (ab[j] >= mid);
            if (bsum(c) >= KTOP) lo = mid; else hi = mid - 1;
        }
        kth = lo;
    }

    int cg = 0;
#pragma unroll
    for (int j = 0; j < 8; j++) cg += (ab[j] > kth);
    cg = bsum(cg);
    const int rem = KTOP - cg;

    int eq = 0;
#pragma unroll
    for (int j = 0; j < 8; j++) eq += (ab[j] == kth);
    int v = eq;
#pragma unroll
    for (int o = 1; o < 32; o <<= 1) {
        int tv = __shfl_up_sync(0xffffffffu, v, o);
        if (lane >= o) v += tv;
    }
    if (lane == 31) shi2[sel][w] = v;
    __syncthreads();
    int off = 0;
    for (int i = 0; i < w; i++) off += shi2[sel][i];
    const int excl = off + v - eq;

    int seen = 0;
#pragma unroll
    for (int j = 0; j < 8; j++) {
        bool keep = (ab[j] > kth) || (ab[j] == kth && (excl + seen) < rem);
        if (ab[j] == kth) seen++;
        if (!keep) a[j] = 0.0f;
    }

    __nv_bfloat162 h0 = __floats2bfloat162_rn(a[0], a[1]);
    __nv_bfloat162 h1 = __floats2bfloat162_rn(a[2], a[3]);
    __nv_bfloat162 h2 = __floats2bfloat162_rn(a[4], a[5]);
    __nv_bfloat162 h3 = __floats2bfloat162_rn(a[6], a[7]);
    uint4 o;
    o.x = ((uint32_t)__bfloat16_as_ushort(h0.y) << 16) | __bfloat16_as_ushort(h0.x);
    o.y = ((uint32_t)__bfloat16_as_ushort(h1.y) << 16) | __bfloat16_as_ushort(h1.x);
    o.z = ((uint32_t)__bfloat16_as_ushort(h2.y) << 16) | __bfloat16_as_ushort(h2.x);
    o.w = ((uint32_t)__bfloat16_as_ushort(h3.y) << 16) | __bfloat16_as_ushort(h3.x);
    *(uint4*)(AB + (size_t)blockIdx.x * LK_ + t * 8) = o;
}

// =====================================================================
// AV via mma.sync bf16 HMMA.
// =====================================================================
__global__ __launch_bounds__(256, 4)
void av_hmma_kernel(const __nv_bfloat16* __restrict__ attn,
                    const __nv_bfloat16* __restrict__ vb,
                    float* __restrict__ ctx)
{
    __shared__ char sm[2 * 24576];
    const uint32_t sb = smem_u32(sm);

    const int t    = threadIdx.x;
    const int lane = t & 31;
    const int w    = t >> 5;
    const int z    = blockIdx.z;
    const int m0   = blockIdx.y * 128;
    const int bb   = z >> 3, hh = z & 7;

    const char* Ag = (const char*)(attn + ((size_t)z * LQ_ + m0) * LK_);
    const char* Vg = (const char*)(vb + (size_t)z * LK_ * DH_);

    const int ar = t >> 1, ah = t & 1;
    const int br = t >> 2, bq = t & 3;

    float acc[8][4];
#pragma unroll
    for (int i = 0; i < 8; i++)
#pragma unroll
        for (int j = 0; j < 4; j++) acc[i][j] = 0.0f;

    uint4 apre[4]; uint4 bpre[2];
    auto prefetch = [&](int c) {
        const char* a = Ag + (size_t)ar * (LK_ * 2) + c * 128 + ah * 64;
#pragma unroll
        for (int i = 0; i < 4; i++) apre[i] = *(const uint4*)(a + i * 16);
        const char* b = Vg + (size_t)(c * 64 + br) * (DH_ * 2) + bq * 32;
#pragma unroll
        for (int i = 0; i < 2; i++) bpre[i] = *(const uint4*)(b + i * 16);
    };
    auto store_sm = [&](int p) {
        char* base = sm + p * 24576;
#pragma unroll
        for (int i = 0; i < 4; i++)
            *(uint4*)(base + swz128((uint32_t)(ar * 128 + ah * 64 + i * 16))) = apre[i];
#pragma unroll
        for (int i = 0; i < 2; i++)
            *(uint4*)(base + 16384 + swz128((uint32_t)(br * 128 + bq * 32 + i * 16))) = bpre[i];
    };

    const int lm = lane >> 3, lr = lane & 7;
    const uint32_t a_row  = (uint32_t)(w * 16 + (lm & 1) * 8 + lr);
    const uint32_t a_colp = (uint32_t)((lm >> 1) * 16);
    const uint32_t b_rowp = (uint32_t)((lm & 1) * 8 + lr);
    const uint32_t b_colp = (uint32_t)((lm >> 1) * 16);

    prefetch(0); store_sm(0);
    prefetch(1);
    __syncthreads();

    for (int c = 0; c < 32; c++) {
        const int p = c & 1;
        if (c < 31) store_sm(p ^ 1);
        if (c < 30) prefetch(c + 2);

        const uint32_t abase = sb + p * 24576;
        const uint32_t bbase = abase + 16384;
#pragma unroll
        for (int ks = 0; ks < 4; ks++) {
            uint32_t a0, a1, a2, a3;
            {
                uint32_t addr = abase + swz128(a_row * 128 + ks * 32 + a_colp);
                asm volatile("ldmatrix.sync.aligned.m8n8.x4.shared.b16 {%0,%1,%2,%3}, [%4];"
                             : "=r"(a0), "=r"(a1), "=r"(a2), "=r"(a3) : "r"(addr));
            }
#pragma unroll
            for (int np = 0; np < 4; np++) {
                uint32_t b0, b1, b2, b3;
                uint32_t addr = bbase + swz128((ks * 16 + b_rowp) * 128 + np * 32 + b_colp);
                asm volatile("ldmatrix.sync.aligned.m8n8.x4.trans.shared.b16 {%0,%1,%2,%3}, [%4];"
                             : "=r"(b0), "=r"(b1), "=r"(b2), "=r"(b3) : "r"(addr));
                asm volatile("mma.sync.aligned.m16n8k16.row.col.f32.bf16.bf16.f32 "
                             "{%0,%1,%2,%3}, {%4,%5,%6,%7}, {%8,%9}, {%0,%1,%2,%3};"
                             : "+f"(acc[2*np][0]), "+f"(acc[2*np][1]), "+f"(acc[2*np][2]), "+f"(acc[2*np][3])
                             : "r"(a0), "r"(a1), "r"(a2), "r"(a3), "r"(b0), "r"(b1));
                asm volatile("mma.sync.aligned.m16n8k16.row.col.f32.bf16.bf16.f32 "
                             "{%0,%1,%2,%3}, {%4,%5,%6,%7}, {%8,%9}, {%0,%1,%2,%3};"
                             : "+f"(acc[2*np+1][0]), "+f"(acc[2*np+1][1]), "+f"(acc[2*np+1][2]), "+f"(acc[2*np+1][3])
                             : "r"(a0), "r"(a1), "r"(a2), "r"(a3), "r"(b2), "r"(b3));
            }
        }
        __syncthreads();
    }

    const int r0 = lane >> 2, c0 = (lane & 3) * 2;
    const int mrow = m0 + w * 16 + r0;
    float* dst0 = ctx + (size_t)(bb * LQ_ + mrow) * D_ + hh * DH_ + c0;
    float* dst1 = dst0 + 8 * D_;
#pragma unroll
    for (int nt = 0; nt < 8; nt++) {
        *(float2*)(dst0 + nt * 8) = make_float2(acc[nt][0], acc[nt][1]);
        *(float2*)(dst1 + nt * 8) = make_float2(acc[nt][2], acc[nt][3]);
    }
}

// =====================================================================
// host launcher
// =====================================================================
extern "C" void kernel_launch(void* const* d_in, const int* in_sizes, int n_in,
                              void* d_out, int out_size)
{
    (void)in_sizes; (void)n_in; (void)out_size;
    const float* q_in = (const float*)d_in[0];
    const float* k_in = (const float*)d_in[1];
    const float* v_in = (const float*)d_in[2];
    const float* Wq   = (const float*)d_in[3];
    const float* bq   = (const float*)d_in[4];
    const float* Wk   = (const float*)d_in[5];
    const float* bk   = (const float*)d_in[6];
    const float* Wv   = (const float*)d_in[7];
    const float* bv   = (const float*)d_in[8];
    const float* Wo   = (const float*)d_in[9];
    const float* bo   = (const float*)d_in[10];
    float* out = (float*)d_out;

    float *qn, *kn, *sc, *ctx;
    __half *qhp, *qlp, *khp, *klp;
    __nv_bfloat16 *vb, *ab;
    cudaGetSymbolAddress((void**)&qn,  g_qn);
    cudaGetSymbolAddress((void**)&kn,  g_kn);
    cudaGetSymbolAddress((void**)&qhp, g_qh);
    cudaGetSymbolAddress((void**)&qlp, g_ql);
    cudaGetSymbolAddress((void**)&khp, g_kh);
    cudaGetSymbolAddress((void**)&klp, g_kl);
    cudaGetSymbolAddress((void**)&vb,  g_vb);
    cudaGetSymbolAddress((void**)&sc,  g_sc);
    cudaGetSymbolAddress((void**)&ab,  g_ab);
    cudaGetSymbolAddress((void**)&ctx, g_ctx);

    const int M = B_ * LQ_;   // 8192

    // 1-3. projections: q,k -> fp32 [b,h,l,e]; v -> tanh -> bf16 [b,h,l,e]
    dim3 gproj(D_ / 128, M / 128, 1);
    gemm_bt_kernel<0><<<gproj, 256>>>(q_in, Wq, bq, qn, M, D_, D_, D_, D_);
    gemm_bt_kernel<0><<<gproj, 256>>>(k_in, Wk, bk, kn, M, D_, D_, D_, D_);
    gemm_bt_kernel<3><<<gproj, 256>>>(v_in, Wv, bv, (float*)vb, M, D_, D_, D_, D_);

    // 4-5. qk-norm + fp16 hi/lo split
    const int nrows = B_ * H_ * LQ_;
    l2norm_split_kernel<<<nrows / 8, 256>>>(qn, qhp, qlp, nrows);
    l2norm_split_kernel<<<nrows / 8, 256>>>(kn, khp, klp, nrows);

    // 6. logits on tensor cores (fp16 split, fp32-exact class)
    dim3 glog(LK_ / 64, LQ_ / 128, B_ * H_);
    logits_hmma_kernel<<<glog, 256>>>(qhp, qlp, khp, klp, sc);

    // 7. softmax + smoothing + gate + exact top-k -> bf16 attn
    softmax_topk_kernel<<<B_ * H_ * LQ_, 256>>>(sc, ab);

    // 8. AV on tensor cores (bf16) -> merged-head fp32 ctx
    dim3 gav(1, LQ_ / 128, B_ * H_);
    av_hmma_kernel<<<gav, 256>>>(ab, vb, ctx);

    // 9. output projection + bias -> d_out
    gemm_bt_kernel<2><<<gproj, 256>>>(ctx, Wo, bo, out, M, D_, D_, D_, D_);
}

// round 6
// speedup vs baseline: 1.5235x; 1.1822x over previous
#include <cuda_runtime.h>
#include <cuda_bf16.h>
#include <cuda_fp16.h>
#include <math.h>
#include <stdint.h>

// ---------------- problem constants ----------------
#define B_    4
#define H_    8
#define LQ_   2048
#define LK_   2048
#define DH_   64
#define D_    512
#define KTOP  205

// ---------------- device scratch (no allocations allowed) ----------------
__device__ __half         g_qih[(size_t)B_ * LQ_ * D_];          // 8 MB input splits
__device__ __half         g_qil[(size_t)B_ * LQ_ * D_];
__device__ __half         g_kih[(size_t)B_ * LK_ * D_];
__device__ __half         g_kil[(size_t)B_ * LK_ * D_];
__device__ __half         g_vih[(size_t)B_ * LK_ * D_];
__device__ __half         g_vil[(size_t)B_ * LK_ * D_];
__device__ __half         g_wqh[D_ * D_], g_wql[D_ * D_];        // weight splits
__device__ __half         g_wkh[D_ * D_], g_wkl[D_ * D_];
__device__ __half         g_wvh[D_ * D_], g_wvl[D_ * D_];
__device__ __half         g_woh[D_ * D_], g_wol[D_ * D_];
__device__ __half         g_qh [(size_t)B_ * H_ * LQ_ * DH_];    // normalized q/k splits
__device__ __half         g_ql [(size_t)B_ * H_ * LQ_ * DH_];
__device__ __half         g_kh [(size_t)B_ * H_ * LK_ * DH_];
__device__ __half         g_kl [(size_t)B_ * H_ * LK_ * DH_];
__device__ __nv_bfloat16  g_vb [(size_t)B_ * H_ * LK_ * DH_];    // v bf16 [z][l][e]
__device__ float          g_sc [(size_t)B_ * H_ * LQ_ * LK_];    // 512 MB fp32 scores
__device__ __nv_bfloat16  g_ab [(size_t)B_ * H_ * LQ_ * LK_];    // 256 MB bf16 attn
__device__ __half         g_cth[(size_t)B_ * LQ_ * D_];          // ctx hi/lo fp16
__device__ __half         g_ctl[(size_t)B_ * LQ_ * D_];

// ---------------- helpers ----------------
__device__ __forceinline__ uint32_t smem_u32(const void* p) {
    uint32_t a;
    asm("{ .reg .u64 t; cvta.to.shared.u64 t, %1; cvt.u32.u64 %0, t; }" : "=r"(a) : "l"(p));
    return a;
}
__device__ __forceinline__ uint32_t swz128(uint32_t o) { return o ^ ((o >> 3) & 0x70); }

#define CP_ASYNC16(dst, src) \
    asm volatile("cp.async.cg.shared.global [%0], [%1], 16;" :: "r"(dst), "l"(src))
#define CP_COMMIT()  asm volatile("cp.async.commit_group;")
#define CP_WAIT1()   asm volatile("cp.async.wait_group 1;")
#define CP_WAIT0()   asm volatile("cp.async.wait_group 0;")

// accurate expf, fast-math-proof (~1 ulp)
__device__ __forceinline__ float exp_rn(float x) {
    if (x < -87.0f) return 0.0f;
    float n = rintf(__fmul_rn(x, 1.4426950408889634f));
    float f = __fmaf_rn(-n, 0.6931471824645996f, x);
    f = __fmaf_rn(-n, -1.9046543e-09f, f);
    float p = 1.9841269841e-04f;
    p = __fmaf_rn(p, f, 1.3888888889e-03f);
    p = __fmaf_rn(p, f, 8.3333333333e-03f);
    p = __fmaf_rn(p, f, 4.1666666667e-02f);
    p = __fmaf_rn(p, f, 1.6666666667e-01f);
    p = __fmaf_rn(p, f, 0.5f);
    p = __fmaf_rn(p, f, 1.0f);
    p = __fmaf_rn(p, f, 1.0f);
    return ldexpf(p, (int)n);
}

__device__ __forceinline__ void split_one(float v, __half& h, __half& l) {
    h = __float2half_rn(v);
    l = __float2half_rn(__fmul_rn(__fadd_rn(v, -__half2float(h)), 2048.0f));
}

// ---------------- fp32 -> fp16 hi/lo split conversion ----------------
__global__ __launch_bounds__(256)
void split_f32_kernel(const float4* __restrict__ S, __half2* __restrict__ Hh,
                      __half2* __restrict__ Hl, int n4)
{
    int i = blockIdx.x * blockDim.x + threadIdx.x;
    if (i >= n4) return;
    float4 v = S[i];
    __half h0, h1, h2, h3, l0, l1, l2, l3;
    split_one(v.x, h0, l0); split_one(v.y, h1, l1);
    split_one(v.z, h2, l2); split_one(v.w, h3, l3);
    Hh[i * 2]     = __halves2half2(h0, h1);
    Hh[i * 2 + 1] = __halves2half2(h2, h3);
    Hl[i * 2]     = __halves2half2(l0, l1);
    Hl[i * 2 + 1] = __halves2half2(l2, l3);
}

// =====================================================================
// Split-fp16 HMMA GEMM (fp32-exact class):
// C = A(Mx512) @ B(N=512 x 512)^T via 3 passes: hh + 2^-11*(hl+lh).
// Tile 128(M) x 64(N); K chunks of 32, cp.async double-buffered.
// smem row (128B): bytes [0,64) = hi, [64,128) = lo.
// EPI 0: q/k proj: +bias, L2-normalize the 64-col head row, emit hi/lo fp16
// EPI 2: out proj: +bias -> fp32 C1[m*512+n]
// EPI 3: v proj:   tanh(+bias) -> bf16 [b,h,l,e]
// =====================================================================
template<int EPI>
__global__ __launch_bounds__(256, 2)
void gemm_split_kernel(const __half* __restrict__ Ah, const __half* __restrict__ Al,
                       const __half* __restrict__ Bh, const __half* __restrict__ Bl,
                       const float* __restrict__ bias,
                       void* __restrict__ C1, void* __restrict__ C2)
{
    __shared__ char sm[49152];
    const uint32_t sb = smem_u32(sm);
    const int t = threadIdx.x, lane = t & 31, w = t >> 5;
    const int m0 = blockIdx.y * 128, n0 = blockIdx.x * 64;

    // cp.async thread mapping
    const int arow = t >> 1, apr = t & 1;
    const int brow = t >> 2, bqr = t & 3;
    const __half* gah = Ah + (size_t)(m0 + arow) * 512 + apr * 16;
    const __half* gal = Al + (size_t)(m0 + arow) * 512 + apr * 16;
    const __half* gbh = Bh + (size_t)(n0 + brow) * 512 + bqr * 8;
    const __half* gbl = Bl + (size_t)(n0 + brow) * 512 + bqr * 8;

    const uint32_t a_d0 = swz128((uint32_t)(arow * 128 + apr * 32));
    const uint32_t a_d1 = swz128((uint32_t)(arow * 128 + apr * 32 + 16));
    const uint32_t a_e0 = swz128((uint32_t)(arow * 128 + 64 + apr * 32));
    const uint32_t a_e1 = swz128((uint32_t)(arow * 128 + 64 + apr * 32 + 16));
    const uint32_t b_d0 = swz128((uint32_t)(brow * 128 + bqr * 16));
    const uint32_t b_e0 = swz128((uint32_t)(brow * 128 + 64 + bqr * 16));

    auto issue = [&](int c, int p) {
        const uint32_t ab = sb + p * 24576;
        const uint32_t bbs = ab + 16384;
        CP_ASYNC16(ab + a_d0, gah + c * 32);
        CP_ASYNC16(ab + a_d1, gah + c * 32 + 8);
        CP_ASYNC16(ab + a_e0, gal + c * 32);
        CP_ASYNC16(ab + a_e1, gal + c * 32 + 8);
        CP_ASYNC16(bbs + b_d0, gbh + c * 32);
        CP_ASYNC16(bbs + b_e0, gbl + c * 32);
        CP_COMMIT();
    };

    float hh[8][4], md[8][4];
#pragma unroll
    for (int g = 0; g < 8; g++)
#pragma unroll
        for (int j = 0; j < 4; j++) { hh[g][j] = 0.0f; md[g][j] = 0.0f; }

    const int lm = lane >> 3, lr = lane & 7;
    const uint32_t a_row  = (uint32_t)(w * 16 + (lm & 1) * 8 + lr);
    const uint32_t a_colp = (uint32_t)((lm >> 1) * 16);
    const uint32_t b_rowp = (uint32_t)((lm >> 1) * 8 + lr);
    const uint32_t b_half = (uint32_t)((lm & 1) * 16);

    issue(0, 0);
    issue(1, 1);

    for (int c = 0; c < 16; c++) {
        if (c < 15) { CP_WAIT1(); } else { CP_WAIT0(); }
        __syncthreads();
        const uint32_t ab = sb + (c & 1) * 24576;
        const uint32_t bbs = ab + 16384;
#pragma unroll
        for (int ks = 0; ks < 2; ks++) {
            uint32_t ah0, ah1, ah2, ah3, al0, al1, al2, al3;
            {
                uint32_t ao  = swz128(a_row * 128 + ks * 32 + a_colp);
                uint32_t aol = swz128(a_row * 128 + 64 + ks * 32 + a_colp);
                asm volatile("ldmatrix.sync.aligned.m8n8.x4.shared.b16 {%0,%1,%2,%3}, [%4];"
                             : "=r"(ah0), "=r"(ah1), "=r"(ah2), "=r"(ah3) : "r"(ab + ao));
                asm volatile("ldmatrix.sync.aligned.m8n8.x4.shared.b16 {%0,%1,%2,%3}, [%4];"
                             : "=r"(al0), "=r"(al1), "=r"(al2), "=r"(al3) : "r"(ab + aol));
            }
#pragma unroll
            for (int np = 0; np < 4; np++) {
                uint32_t bo  = swz128((np * 16 + b_rowp) * 128 + ks * 32 + b_half);
                uint32_t bol = swz128((np * 16 + b_rowp) * 128 + 64 + ks * 32 + b_half);
                uint32_t bh0, bh1, bh2, bh3, bl0, bl1, bl2, bl3;
                asm volatile("ldmatrix.sync.aligned.m8n8.x4.shared.b16 {%0,%1,%2,%3}, [%4];"
                             : "=r"(bh0), "=r"(bh1), "=r"(bh2), "=r"(bh3) : "r"(bbs + bo));
                asm volatile("ldmatrix.sync.aligned.m8n8.x4.shared.b16 {%0,%1,%2,%3}, [%4];"
                             : "=r"(bl0), "=r"(bl1), "=r"(bl2), "=r"(bl3) : "r"(bbs + bol));
#define MMA_F16(ACC, A0,A1,A2,A3, B0,B1) \
    asm volatile("mma.sync.aligned.m16n8k16.row.col.f32.f16.f16.f32 " \
                 "{%0,%1,%2,%3}, {%4,%5,%6,%7}, {%8,%9}, {%0,%1,%2,%3};" \
                 : "+f"((ACC)[0]), "+f"((ACC)[1]), "+f"((ACC)[2]), "+f"((ACC)[3]) \
                 : "r"(A0), "r"(A1), "r"(A2), "r"(A3), "r"(B0), "r"(B1))
                MMA_F16(hh[np*2+0], ah0,ah1,ah2,ah3, bh0,bh1);
                MMA_F16(hh[np*2+1], ah0,ah1,ah2,ah3, bh2,bh3);
                MMA_F16(md[np*2+0], ah0,ah1,ah2,ah3, bl0,bl1);
                MMA_F16(md[np*2+1], ah0,ah1,ah2,ah3, bl2,bl3);
                MMA_F16(md[np*2+0], al0,al1,al2,al3, bh0,bh1);
                MMA_F16(md[np*2+1], al0,al1,al2,al3, bh2,bh3);
#undef MMA_F16
            }
        }
        __syncthreads();
        if (c + 2 < 16) issue(c + 2, c & 1);
    }

    // ---- epilogue ----
    const float INV = 4.8828125e-04f;  // 2^-11
    const int r0  = lane >> 2, c0l = (lane & 3) * 2;
    const int mA  = m0 + w * 16 + r0;
    const int mB  = mA + 8;

    float va[8][2], vb2[8][2];
#pragma unroll
    for (int nt = 0; nt < 8; nt++) {
        const float b0 = bias[n0 + nt * 8 + c0l];
        const float b1 = bias[n0 + nt * 8 + c0l + 1];
        va[nt][0]  = __fadd_rn(__fmaf_rn(md[nt][0], INV, hh[nt][0]), b0);
        va[nt][1]  = __fadd_rn(__fmaf_rn(md[nt][1], INV, hh[nt][1]), b1);
        vb2[nt][0] = __fadd_rn(__fmaf_rn(md[nt][2], INV, hh[nt][2]), b0);
        vb2[nt][1] = __fadd_rn(__fmaf_rn(md[nt][3], INV, hh[nt][3]), b1);
    }

    if (EPI == 0) {
        float s0 = 0.0f, s1 = 0.0f;
#pragma unroll
        for (int nt = 0; nt < 8; nt++) {
            s0 = __fmaf_rn(va[nt][0], va[nt][0], s0);
            s0 = __fmaf_rn(va[nt][1], va[nt][1], s0);
            s1 = __fmaf_rn(vb2[nt][0], vb2[nt][0], s1);
            s1 = __fmaf_rn(vb2[nt][1], vb2[nt][1], s1);
        }
        s0 += __shfl_xor_sync(0xffffffffu, s0, 1);
        s0 += __shfl_xor_sync(0xffffffffu, s0, 2);
        s1 += __shfl_xor_sync(0xffffffffu, s1, 1);
        s1 += __shfl_xor_sync(0xffffffffu, s1, 2);
        const float nr0 = fmaxf(__fsqrt_rn(s0), 1e-12f);
        const float nr1 = fmaxf(__fsqrt_rn(s1), 1e-12f);

        __half* Qh = (__half*)C1;
        __half* Ql = (__half*)C2;
        const int bbi = mA >> 11, h = n0 >> 6;
        const size_t rbA = (((size_t)(bbi * H_ + h)) * LQ_ + (mA & (LQ_ - 1))) * DH_;
        const size_t rbB = (((size_t)(bbi * H_ + h)) * LQ_ + (mB & (LQ_ - 1))) * DH_;
#pragma unroll
        for (int nt = 0; nt < 8; nt++) {
            const int col = nt * 8 + c0l;
            float q0 = __fdiv_rn(va[nt][0], nr0);
            float q1 = __fdiv_rn(va[nt][1], nr0);
            float q2 = __fdiv_rn(vb2[nt][0], nr1);
            float q3 = __fdiv_rn(vb2[nt][1], nr1);
            __half h0, h1, h2, h3, l0, l1, l2, l3;
            split_one(q0, h0, l0); split_one(q1, h1, l1);
            split_one(q2, h2, l2); split_one(q3, h3, l3);
            *(__half2*)(Qh + rbA + col) = __halves2half2(h0, h1);
            *(__half2*)(Ql + rbA + col) = __halves2half2(l0, l1);
            *(__half2*)(Qh + rbB + col) = __halves2half2(h2, h3);
            *(__half2*)(Ql + rbB + col) = __halves2half2(l2, l3);
        }
    } else if (EPI == 2) {
        float* O = (float*)C1;
#pragma unroll
        for (int nt = 0; nt < 8; nt++) {
            const int col = n0 + nt * 8 + c0l;
            *(float2*)(O + (size_t)mA * D_ + col) = make_float2(va[nt][0], va[nt][1]);
            *(float2*)(O + (size_t)mB * D_ + col) = make_float2(vb2[nt][0], vb2[nt][1]);
        }
    } else {  // EPI == 3
        __nv_bfloat16* V = (__nv_bfloat16*)C1;
        const int bbi = mA >> 11, h = n0 >> 6;
        const size_t rbA = (((size_t)(bbi * H_ + h)) * LK_ + (mA & (LK_ - 1))) * DH_;
        const size_t rbB = (((size_t)(bbi * H_ + h)) * LK_ + (mB & (LK_ - 1))) * DH_;
#pragma unroll
        for (int nt = 0; nt < 8; nt++) {
            const int col = nt * 8 + c0l;
            *(__nv_bfloat162*)(V + rbA + col) =
                __floats2bfloat162_rn(tanhf(va[nt][0]), tanhf(va[nt][1]));
            *(__nv_bfloat162*)(V + rbB + col) =
                __floats2bfloat162_rn(tanhf(vb2[nt][0]), tanhf(vb2[nt][1]));
        }
    }
}

// =====================================================================
// Logits via fp16 split HMMA (fp32-exact class). Same as R4 (validated).
// =====================================================================
__global__ __launch_bounds__(256, 2)
void logits_hmma_kernel(const __half* __restrict__ qh, const __half* __restrict__ ql,
                        const __half* __restrict__ kh, const __half* __restrict__ kl,
                        float* __restrict__ sc)
{
    __shared__ char sm[49152];   // Ah 16K | Al 16K | Bh 8K | Bl 8K
    const uint32_t sb = smem_u32(sm);
    const int t = threadIdx.x, lane = t & 31, w = t >> 5;
    const int z  = blockIdx.z;
    const int m0 = blockIdx.y * 128;
    const int n0 = blockIdx.x * 64;

    const char* Aqh = (const char*)(qh + ((size_t)z * LQ_ + m0) * DH_);
    const char* Aql = (const char*)(ql + ((size_t)z * LQ_ + m0) * DH_);
    const char* Bkh = (const char*)(kh + ((size_t)z * LK_ + n0) * DH_);
    const char* Bkl = (const char*)(kl + ((size_t)z * LK_ + n0) * DH_);

    {
        const int r = t >> 1, hf = t & 1;
        const char* sh = Aqh + (size_t)r * 128 + hf * 64;
        const char* sl = Aql + (size_t)r * 128 + hf * 64;
#pragma unroll
        for (int i = 0; i < 4; i++) {
            uint32_t off = swz128((uint32_t)(r * 128 + hf * 64 + i * 16));
            *(uint4*)(sm + off)         = *(const uint4*)(sh + i * 16);
            *(uint4*)(sm + 16384 + off) = *(const uint4*)(sl + i * 16);
        }
    }
    {
        const int r = t >> 2, qq = t & 3;
        const char* sh = Bkh + (size_t)r * 128 + qq * 32;
        const char* sl = Bkl + (size_t)r * 128 + qq * 32;
#pragma unroll
        for (int i = 0; i < 2; i++) {
            uint32_t off = swz128((uint32_t)(r * 128 + qq * 32 + i * 16));
            *(uint4*)(sm + 32768 + off) = *(const uint4*)(sh + i * 16);
            *(uint4*)(sm + 40960 + off) = *(const uint4*)(sl + i * 16);
        }
    }
    __syncthreads();

    float hh[8][4], md[8][4];
#pragma unroll
    for (int g = 0; g < 8; g++)
#pragma unroll
        for (int j = 0; j < 4; j++) { hh[g][j] = 0.0f; md[g][j] = 0.0f; }

    const int lm = lane >> 3, lr = lane & 7;
    const uint32_t a_row  = (uint32_t)(w * 16 + (lm & 1) * 8 + lr);
    const uint32_t a_colp = (uint32_t)((lm >> 1) * 16);
    const uint32_t b_rowp = (uint32_t)((lm >> 1) * 8 + lr);
    const uint32_t b_half = (uint32_t)((lm & 1) * 16);

#pragma unroll
    for (int ks = 0; ks < 4; ks++) {
        uint32_t ah0, ah1, ah2, ah3, al0, al1, al2, al3;
        {
            uint32_t ao = swz128(a_row * 128 + ks * 32 + a_colp);
            asm volatile("ldmatrix.sync.aligned.m8n8.x4.shared.b16 {%0,%1,%2,%3}, [%4];"
                         : "=r"(ah0), "=r"(ah1), "=r"(ah2), "=r"(ah3) : "r"(sb + ao));
            asm volatile("ldmatrix.sync.aligned.m8n8.x4.shared.b16 {%0,%1,%2,%3}, [%4];"
                         : "=r"(al0), "=r"(al1), "=r"(al2), "=r"(al3) : "r"(sb + 16384 + ao));
        }
#pragma unroll
        for (int np = 0; np < 4; np++) {
            uint32_t bo = swz128((np * 16 + b_rowp) * 128 + ks * 32 + b_half);
            uint32_t bh0, bh1, bh2, bh3, bl0, bl1, bl2, bl3;
            asm volatile("ldmatrix.sync.aligned.m8n8.x4.shared.b16 {%0,%1,%2,%3}, [%4];"
                         : "=r"(bh0), "=r"(bh1), "=r"(bh2), "=r"(bh3) : "r"(sb + 32768 + bo));
            asm volatile("ldmatrix.sync.aligned.m8n8.x4.shared.b16 {%0,%1,%2,%3}, [%4];"
                         : "=r"(bl0), "=r"(bl1), "=r"(bl2), "=r"(bl3) : "r"(sb + 40960 + bo));
#define MMA_F16(ACC, A0,A1,A2,A3, B0,B1) \
    asm volatile("mma.sync.aligned.m16n8k16.row.col.f32.f16.f16.f32 " \
                 "{%0,%1,%2,%3}, {%4,%5,%6,%7}, {%8,%9}, {%0,%1,%2,%3};" \
                 : "+f"((ACC)[0]), "+f"((ACC)[1]), "+f"((ACC)[2]), "+f"((ACC)[3]) \
                 : "r"(A0), "r"(A1), "r"(A2), "r"(A3), "r"(B0), "r"(B1))
            MMA_F16(hh[np*2+0], ah0,ah1,ah2,ah3, bh0,bh1);
            MMA_F16(hh[np*2+1], ah0,ah1,ah2,ah3, bh2,bh3);
            MMA_F16(md[np*2+0], ah0,ah1,ah2,ah3, bl0,bl1);
            MMA_F16(md[np*2+1], ah0,ah1,ah2,ah3, bl2,bl3);
            MMA_F16(md[np*2+0], al0,al1,al2,al3, bh0,bh1);
            MMA_F16(md[np*2+1], al0,al1,al2,al3, bh2,bh3);
#undef MMA_F16
        }
    }

    const float INV = 4.8828125e-04f;
    const int r0 = lane >> 2, c0 = (lane & 3) * 2;
    float* base0 = sc + ((size_t)z * LQ_ + m0 + w * 16 + r0) * (size_t)LK_ + n0 + c0;
    float* base1 = base0 + 8 * (size_t)LK_;
#pragma unroll
    for (int g = 0; g < 8; g++) {
        float2 v0, v1;
        v0.x = __fmul_rn(__fmaf_rn(md[g][0], INV, hh[g][0]), 0.125f);
        v0.y = __fmul_rn(__fmaf_rn(md[g][1], INV, hh[g][1]), 0.125f);
        v1.x = __fmul_rn(__fmaf_rn(md[g][2], INV, hh[g][2]), 0.125f);
        v1.y = __fmul_rn(__fmaf_rn(md[g][3], INV, hh[g][3]), 0.125f);
        *(float2*)(base0 + g * 8) = v0;
        *(float2*)(base1 + g * 8) = v1;
    }
}

// =====================================================================
// Per-row: softmax -> smoothing -> gate -> exact top-205 mask -> bf16 out.
// =====================================================================
__global__ __launch_bounds__(256)
void softmax_topk_kernel(const float* __restrict__ S, __nv_bfloat16* __restrict__ AB)
{
    __shared__ float shf[8];
    __shared__ int   shi2[2][8];
    __shared__ float bcf;

    const int t    = threadIdx.x;
    const int lane = t & 31;
    const int w    = t >> 5;
    const float* row = S + (size_t)blockIdx.x * LK_;

    float x[8];
    *(float4*)(x)     = *(const float4*)(row + t * 8);
    *(float4*)(x + 4) = *(const float4*)(row + t * 8 + 4);

    float m = x[0];
#pragma unroll
    for (int j = 1; j < 8; j++) m = fmaxf(m, x[j]);
#pragma unroll
    for (int o = 16; o; o >>= 1) m = fmaxf(m, __shfl_xor_sync(0xffffffffu, m, o));
    if (lane == 0) shf[w] = m;
    __syncthreads();
    if (t == 0) { float mm = shf[0];
#pragma unroll
        for (int i = 1; i < 8; i++) mm = fmaxf(mm, shf[i]);
        bcf = mm; }
    __syncthreads();
    m = bcf;

    float e[8]; float s = 0.0f;
#pragma unroll
    for (int j = 0; j < 8; j++) { e[j] = exp_rn(__fadd_rn(x[j], -m)); s = __fadd_rn(s, e[j]); }
#pragma unroll
    for (int o = 16; o; o >>= 1) s += __shfl_xor_sync(0xffffffffu, s, o);
    if (lane == 0) shf[w] = s;
    __syncthreads();
    if (t == 0) { float ss = 0.0f;
#pragma unroll
        for (int i = 0; i < 8; i++) ss = __fadd_rn(ss, shf[i]);
        bcf = ss; }
    __syncthreads();
    s = bcf;

    const float SMC = 4.8828125e-06f;
    float a[8]; unsigned ab[8];
#pragma unroll
    for (int j = 0; j < 8; j++) {
        float p = __fdiv_rn(e[j], s);
        float q = __fadd_rn(__fmul_rn(0.99f, p), SMC);
        a[j]  = (q >= 1e-4f) ? q : 0.0f;
        ab[j] = __float_as_uint(a[j]);
    }

    int sel = 0;
    auto bsum = [&](int c) -> int {
        c = __reduce_add_sync(0xffffffffu, c);
        if (lane == 0) shi2[sel][w] = c;
        __syncthreads();
        int s2 = 0;
#pragma unroll
        for (int i = 0; i < 8; i++) s2 += shi2[sel][i];
        sel ^= 1;
        return s2;
    };

    const unsigned BLO = __float_as_uint(1e-4f);
    int cnt = 0;
#pragma unroll
    for (int j = 0; j < 8; j++) cnt += (ab[j] >= BLO);
    const int c0 = bsum(cnt);

    unsigned kth = 0u;
    if (c0 >= KTOP) {
        // exact row max of a: max prob = 1/s (exp(0)=1), so amax = 0.99/s + SMC
        const float amax = __fadd_rn(__fmul_rn(0.99f, __fdiv_rn(1.0f, s)), SMC);
        unsigned lo = BLO, hi = __float_as_uint(amax);
        while (lo < hi) {
            unsigned mid = lo + ((hi - lo + 1) >> 1);
            int c = 0;
#pragma unroll
            for (int j = 0; j < 8; j++) c += (ab[j] >= mid);
            if (bsum(c) >= KTOP) lo = mid; else hi = mid - 1;
        }
        kth = lo;
    }

    int cg = 0;
#pragma unroll
    for (int j = 0; j < 8; j++) cg += (ab[j] > kth);
    cg = bsum(cg);
    const int rem = KTOP - cg;

    int eq = 0;
#pragma unroll
    for (int j = 0; j < 8; j++) eq += (ab[j] == kth);
    int v = eq;
#pragma unroll
    for (int o = 1; o < 32; o <<= 1) {
        int tv = __shfl_up_sync(0xffffffffu, v, o);
        if (lane >= o) v += tv;
    }
    if (lane == 31) shi2[sel][w] = v;
    __syncthreads();
    int off = 0;
    for (int i = 0; i < w; i++) off += shi2[sel][i];
    const int excl = off + v - eq;

    int seen = 0;
#pragma unroll
    for (int j = 0; j < 8; j++) {
        bool keep = (ab[j] > kth) || (ab[j] == kth && (excl + seen) < rem);
        if (ab[j] == kth) seen++;
        if (!keep) a[j] = 0.0f;
    }

    __nv_bfloat162 h0 = __floats2bfloat162_rn(a[0], a[1]);
    __nv_bfloat162 h1 = __floats2bfloat162_rn(a[2], a[3]);
    __nv_bfloat162 h2 = __floats2bfloat162_rn(a[4], a[5]);
    __nv_bfloat162 h3 = __floats2bfloat162_rn(a[6], a[7]);
    uint4 o;
    o.x = ((uint32_t)__bfloat16_as_ushort(h0.y) << 16) | __bfloat16_as_ushort(h0.x);
    o.y = ((uint32_t)__bfloat16_as_ushort(h1.y) << 16) | __bfloat16_as_ushort(h1.x);
    o.z = ((uint32_t)__bfloat16_as_ushort(h2.y) << 16) | __bfloat16_as_ushort(h2.x);
    o.w = ((uint32_t)__bfloat16_as_ushort(h3.y) << 16) | __bfloat16_as_ushort(h3.x);
    *(uint4*)(AB + (size_t)blockIdx.x * LK_ + t * 8) = o;
}

// =====================================================================
// AV via mma.sync bf16 HMMA -> ctx hi/lo fp16 (feeds split out-proj).
// =====================================================================
__global__ __launch_bounds__(256, 4)
void av_hmma_kernel(const __nv_bfloat16* __restrict__ attn,
                    const __nv_bfloat16* __restrict__ vb,
                    __half* __restrict__ cth, __half* __restrict__ ctl)
{
    __shared__ char sm[2 * 24576];
    const uint32_t sb = smem_u32(sm);

    const int t    = threadIdx.x;
    const int lane = t & 31;
    const int w    = t >> 5;
    const int z    = blockIdx.z;
    const int m0   = blockIdx.y * 128;
    const int bb   = z >> 3, hh = z & 7;

    const char* Ag = (const char*)(attn + ((size_t)z * LQ_ + m0) * LK_);
    const char* Vg = (const char*)(vb + (size_t)z * LK_ * DH_);

    const int ar = t >> 1, ah = t & 1;
    const int br = t >> 2, bq = t & 3;

    float acc[8][4];
#pragma unroll
    for (int i = 0; i < 8; i++)
#pragma unroll
        for (int j = 0; j < 4; j++) acc[i][j] = 0.0f;

    uint4 apre[4]; uint4 bpre[2];
    auto prefetch = [&](int c) {
        const char* a = Ag + (size_t)ar * (LK_ * 2) + c * 128 + ah * 64;
#pragma unroll
        for (int i = 0; i < 4; i++) apre[i] = *(const uint4*)(a + i * 16);
        const char* b = Vg + (size_t)(c * 64 + br) * (DH_ * 2) + bq * 32;
#pragma unroll
        for (int i = 0; i < 2; i++) bpre[i] = *(const uint4*)(b + i * 16);
    };
    auto store_sm = [&](int p) {
        char* base = sm + p * 24576;
#pragma unroll
        for (int i = 0; i < 4; i++)
            *(uint4*)(base + swz128((uint32_t)(ar * 128 + ah * 64 + i * 16))) = apre[i];
#pragma unroll
        for (int i = 0; i < 2; i++)
            *(uint4*)(base + 16384 + swz128((uint32_t)(br * 128 + bq * 32 + i * 16))) = bpre[i];
    };

    const int lm = lane >> 3, lr = lane & 7;
    const uint32_t a_row  = (uint32_t)(w * 16 + (lm & 1) * 8 + lr);
    const uint32_t a_colp = (uint32_t)((lm >> 1) * 16);
    const uint32_t b_rowp = (uint32_t)((lm & 1) * 8 + lr);
    const uint32_t b_colp = (uint32_t)((lm >> 1) * 16);

    prefetch(0); store_sm(0);
    prefetch(1);
    __syncthreads();

    for (int c = 0; c < 32; c++) {
        const int p = c & 1;
        if (c < 31) store_sm(p ^ 1);
        if (c < 30) prefetch(c + 2);

        const uint32_t abase = sb + p * 24576;
        const uint32_t bbase = abase + 16384;
#pragma unroll
        for (int ks = 0; ks < 4; ks++) {
            uint32_t a0, a1, a2, a3;
            {
                uint32_t addr = abase + swz128(a_row * 128 + ks * 32 + a_colp);
                asm volatile("ldmatrix.sync.aligned.m8n8.x4.shared.b16 {%0,%1,%2,%3}, [%4];"
                             : "=r"(a0), "=r"(a1), "=r"(a2), "=r"(a3) : "r"(addr));
            }
#pragma unroll
            for (int np = 0; np < 4; np++) {
                uint32_t b0, b1, b2, b3;
                uint32_t addr = bbase + swz128((ks * 16 + b_rowp) * 128 + np * 32 + b_colp);
                asm volatile("ldmatrix.sync.aligned.m8n8.x4.trans.shared.b16 {%0,%1,%2,%3}, [%4];"
                             : "=r"(b0), "=r"(b1), "=r"(b2), "=r"(b3) : "r"(addr));
                asm volatile("mma.sync.aligned.m16n8k16.row.col.f32.bf16.bf16.f32 "
                             "{%0,%1,%2,%3}, {%4,%5,%6,%7}, {%8,%9}, {%0,%1,%2,%3};"
                             : "+f"(acc[2*np][0]), "+f"(acc[2*np][1]), "+f"(acc[2*np][2]), "+f"(acc[2*np][3])
                             : "r"(a0), "r"(a1), "r"(a2), "r"(a3), "r"(b0), "r"(b1));
                asm volatile("mma.sync.aligned.m16n8k16.row.col.f32.bf16.bf16.f32 "
                             "{%0,%1,%2,%3}, {%4,%5,%6,%7}, {%8,%9}, {%0,%1,%2,%3};"
                             : "+f"(acc[2*np+1][0]), "+f"(acc[2*np+1][1]), "+f"(acc[2*np+1][2]), "+f"(acc[2*np+1][3])
                             : "r"(a0), "r"(a1), "r"(a2), "r"(a3), "r"(b2), "r"(b3));
            }
        }
        __syncthreads();
    }

    const int r0 = lane >> 2, c0 = (lane & 3) * 2;
    const int mrow = m0 + w * 16 + r0;
    const size_t d0 = (size_t)(bb * LQ_ + mrow) * D_ + hh * DH_ + c0;
    const size_t d1 = d0 + 8 * D_;
#pragma unroll
    for (int nt = 0; nt < 8; nt++) {
        __half h0, h1, h2, h3, l0, l1, l2, l3;
        split_one(acc[nt][0], h0, l0); split_one(acc[nt][1], h1, l1);
        split_one(acc[nt][2], h2, l2); split_one(acc[nt][3], h3, l3);
        *(__half2*)(cth + d0 + nt * 8) = __halves2half2(h0, h1);
        *(__half2*)(ctl + d0 + nt * 8) = __halves2half2(l0, l1);
        *(__half2*)(cth + d1 + nt * 8) = __halves2half2(h2, h3);
        *(__half2*)(ctl + d1 + nt * 8) = __halves2half2(l2, l3);
    }
}

// =====================================================================
// host launcher
// =====================================================================
extern "C" void kernel_launch(void* const* d_in, const int* in_sizes, int n_in,
                              void* d_out, int out_size)
{
    (void)in_sizes; (void)n_in; (void)out_size;
    const float* q_in = (const float*)d_in[0];
    const float* k_in = (const float*)d_in[1];
    const float* v_in = (const float*)d_in[2];
    const float* Wq   = (const float*)d_in[3];
    const float* bq   = (const float*)d_in[4];
    const float* Wk   = (const float*)d_in[5];
    const float* bk   = (const float*)d_in[6];
    const float* Wv   = (const float*)d_in[7];
    const float* bv   = (const float*)d_in[8];
    const float* Wo   = (const float*)d_in[9];
    const float* bo   = (const float*)d_in[10];
    float* out = (float*)d_out;

    __half *qih, *qil, *kih, *kil, *vih, *vil;
    __half *wqh, *wql, *wkh, *wkl, *wvh, *wvl, *woh, *wol;
    __half *qhp, *qlp, *khp, *klp, *cth, *ctl;
    __nv_bfloat16 *vb, *abuf;
    float *sc;
    cudaGetSymbolAddress((void**)&qih, g_qih); cudaGetSymbolAddress((void**)&qil, g_qil);
    cudaGetSymbolAddress((void**)&kih, g_kih); cudaGetSymbolAddress((void**)&kil, g_kil);
    cudaGetSymbolAddress((void**)&vih, g_vih); cudaGetSymbolAddress((void**)&vil, g_vil);
    cudaGetSymbolAddress((void**)&wqh, g_wqh); cudaGetSymbolAddress((void**)&wql, g_wql);
    cudaGetSymbolAddress((void**)&wkh, g_wkh); cudaGetSymbolAddress((void**)&wkl, g_wkl);
    cudaGetSymbolAddress((void**)&wvh, g_wvh); cudaGetSymbolAddress((void**)&wvl, g_wvl);
    cudaGetSymbolAddress((void**)&woh, g_woh); cudaGetSymbolAddress((void**)&wol, g_wol);
    cudaGetSymbolAddress((void**)&qhp, g_qh);  cudaGetSymbolAddress((void**)&qlp, g_ql);
    cudaGetSymbolAddress((void**)&khp, g_kh);  cudaGetSymbolAddress((void**)&klp, g_kl);
    cudaGetSymbolAddress((void**)&vb,  g_vb);  cudaGetSymbolAddress((void**)&sc,  g_sc);
    cudaGetSymbolAddress((void**)&abuf, g_ab);
    cudaGetSymbolAddress((void**)&cth, g_cth); cudaGetSymbolAddress((void**)&ctl, g_ctl);

    const int M = B_ * LQ_;               // 8192
    const int NIN4 = M * D_ / 4;          // 1048576
    const int NW4  = D_ * D_ / 4;         // 65536

    // 0. split conversions (inputs + weights)
    split_f32_kernel<<<NIN4 / 256, 256>>>((const float4*)q_in, (__half2*)qih, (__half2*)qil, NIN4);
    split_f32_kernel<<<NIN4 / 256, 256>>>((const float4*)k_in, (__half2*)kih, (__half2*)kil, NIN4);
    split_f32_kernel<<<NIN4 / 256, 256>>>((const float4*)v_in, (__half2*)vih, (__half2*)vil, NIN4);
    split_f32_kernel<<<NW4 / 256, 256>>>((const float4*)Wq, (__half2*)wqh, (__half2*)wql, NW4);
    split_f32_kernel<<<NW4 / 256, 256>>>((const float4*)Wk, (__half2*)wkh, (__half2*)wkl, NW4);
    split_f32_kernel<<<NW4 / 256, 256>>>((const float4*)Wv, (__half2*)wvh, (__half2*)wvl, NW4);
    split_f32_kernel<<<NW4 / 256, 256>>>((const float4*)Wo, (__half2*)woh, (__half2*)wol, NW4);

    // 1-3. projections on tensor cores (split fp16, fp32-exact class)
    dim3 gproj(D_ / 64, M / 128);
    gemm_split_kernel<0><<<gproj, 256>>>(qih, qil, wqh, wql, bq, qhp, qlp);
    gemm_split_kernel<0><<<gproj, 256>>>(kih, kil, wkh, wkl, bk, khp, klp);
    gemm_split_kernel<3><<<gproj, 256>>>(vih, vil, wvh, wvl, bv, vb, nullptr);

    // 4. logits on tensor cores
    dim3 glog(LK_ / 64, LQ_ / 128, B_ * H_);
    logits_hmma_kernel<<<glog, 256>>>(qhp, qlp, khp, klp, sc);

    // 5. softmax + smoothing + gate + exact top-k -> bf16 attn
    softmax_topk_kernel<<<B_ * H_ * LQ_, 256>>>(sc, abuf);

    // 6. AV on tensor cores -> ctx hi/lo fp16
    dim3 gav(1, LQ_ / 128, B_ * H_);
    av_hmma_kernel<<<gav, 256>>>(abuf, vb, cth, ctl);

    // 7. output projection on tensor cores -> d_out
    gemm_split_kernel<2><<<gproj, 256>>>(cth, ctl, woh, wol, bo, out, nullptr);
}